// round 4
// baseline (speedup 1.0000x reference)
#include <cuda_runtime.h>
#include <math.h>

#define NN 40000
#define EE 320000
#define DD 128
#define HH 4
#define TT 3
#define RR 5
#define KKM 3
#define DKK 32
#define ND (NN*DD)
#define INV_SQRT_DK 0.17677669529663687f   // 1/sqrt(32)
#define LDW 136                             // k-major W plane pitch (pad 8)
#define LDK 68                              // A half-K plane pitch (pad 4)
#define SM_BYTES (2*128*LDW*4 + 2*128*LDK*4)   // 208896 B

// ---------------- scratch (device globals; no allocation allowed) -------------
__device__ float    g_q[ND];
__device__ float    g_k[ND];
__device__ float    g_v[ND];
__device__ float    g_qA[NN*RR*DD];
__device__ float    g_logits[EE*HH];     // logits, then exp() in place
__device__ unsigned g_mx[NN*HH];         // encoded float max
__device__ float    g_sum[NN*HH];
__device__ int      g_deg[NN];
__device__ float    g_agg[KKM*ND];
__device__ float    g_aggm[KKM*ND];
__device__ float    g_front[KKM*ND];
__device__ float    g_tail[KKM*ND];
__device__ float    g_res[ND];
__device__ float    g_trans[ND];
__device__ float    g_Wt[KKM*DD*DD];     // WMk[k] @ Wkl
__device__ float    g_Wf[KKM*DD*DD];     // Wq @ Wak[k]
__device__ float    g_bf[KKM*DD];        // bq @ Wak[k]
__device__ int      g_list[NN];
__device__ int      g_cnt[TT];
__device__ int      g_off[TT];
__device__ int      g_cur[TT];

// ---------------- helpers ----------------
__device__ __forceinline__ unsigned enc_f(float f) {
    unsigned u = __float_as_uint(f);
    return (u & 0x80000000u) ? ~u : (u | 0x80000000u);
}
__device__ __forceinline__ float dec_f(unsigned u) {
    return (u & 0x80000000u) ? __uint_as_float(u & 0x7fffffffu) : __uint_as_float(~u);
}
__device__ __forceinline__ float signed_cbrt(float a) {
    float s = (a > 0.f) ? 1.f : ((a < 0.f) ? -1.f : 0.f);
    return s * cbrtf(fabsf(a) + 1e-18f);
}
__device__ __forceinline__ float gelu_exact(float x) {
    return 0.5f * x * (1.f + erff(x * 0.70710678118654752440f));
}
__device__ __forceinline__ float warp_sum(float p) {
    #pragma unroll
    for (int o = 16; o > 0; o >>= 1) p += __shfl_xor_sync(0xffffffffu, p, o);
    return p;
}
// split x into tf32 hi + tf32 lo (x ≈ hi + lo, residual ~2^-22)
__device__ __forceinline__ void split2(float x, float& hi, float& lo) {
    unsigned uh, ul;
    asm("cvt.rna.tf32.f32 %0, %1;" : "=r"(uh) : "f"(x));
    float h = __uint_as_float(uh);
    float r = x - h;
    asm("cvt.rna.tf32.f32 %0, %1;" : "=r"(ul) : "f"(r));
    hi = h; lo = __uint_as_float(ul);
}

// ---------------- init / bucketing ----------------
__global__ void k_init() {
    int i = blockIdx.x * blockDim.x + threadIdx.x;
    int stride = gridDim.x * blockDim.x;
    for (int j = i; j < NN * HH; j += stride) { g_mx[j] = 0u; g_sum[j] = 0.f; }
    for (int j = i; j < NN; j += stride) g_deg[j] = 0;
    if (i < TT) { g_cnt[i] = 0; g_cur[i] = 0; }
}
__global__ void k_count(const int* __restrict__ nt) {
    int n = blockIdx.x * blockDim.x + threadIdx.x;
    if (n < NN) atomicAdd(&g_cnt[nt[n]], 1);
}
__global__ void k_offs() {
    int o = 0;
    for (int t = 0; t < TT; t++) { g_off[t] = o; g_cur[t] = o; o += g_cnt[t]; }
}
__global__ void k_scatter(const int* __restrict__ nt) {
    int n = blockIdx.x * blockDim.x + threadIdx.x;
    if (n < NN) {
        int p = atomicAdd(&g_cur[nt[n]], 1);
        g_list[p] = n;
    }
}

// ------- 3xTF32 tensor-core GEMM: C[rows] = xform(X[rows]) @ W + B -----------
// 128x128 output tile, K=128. 256 threads = 8 warps (4M x 2N).
// Split-precision: acc += Ahi*Whi + Alo*Whi + Ahi*Wlo  (drops lo*lo ~2^-22).
// typed==1: blockIdx.y = node type; rows gathered from g_list segment.
// typed==0: blockIdx.y = batch idx; pointers advance by *_stride.
// xform: 0 none, 1 signed cbrt, 2 gelu; applied when gy==xform_gy or xform_gy==-2.
__global__ __launch_bounds__(256) void tc_gemm(
    const float* __restrict__ X, long long xs,
    const float* __restrict__ W, long long ws,
    const float* __restrict__ B, long long bs,
    float* __restrict__ C, long long cs,
    int typed, int nrows, int xform, int xform_gy)
{
    extern __shared__ float sm[];
    float* Whi = sm;                       // [128][LDW] k-major
    float* Wlo = sm + 128 * LDW;
    float* Ahi = sm + 2 * 128 * LDW;       // [128][LDK] half-K stage
    float* Alo = Ahi + 128 * LDK;

    int gy = blockIdx.y;
    const int* rows = nullptr;
    int cnt;
    if (typed) {
        rows = g_list + g_off[gy];
        cnt = g_cnt[gy];
        W += (long long)gy * DD * DD;
        if (B) B += (long long)gy * DD;
    } else {
        X += (long long)gy * xs;
        W += (long long)gy * ws;
        if (B) B += (long long)gy * bs;
        C += (long long)gy * cs;
        cnt = nrows;
    }
    int bm = blockIdx.x * 128;
    if (bm >= cnt) return;
    bool doX = xform && (xform_gy == -2 || gy == xform_gy);

    int tid = threadIdx.x, w = tid >> 5, lane = tid & 31;

    // load + split W (full K, k-major planes)
    for (int k = w; k < DD; k += 8) {
        float4 v = *(const float4*)(W + (long long)k * DD + lane * 4);
        float* dh = Whi + k * LDW + lane * 4;
        float* dl = Wlo + k * LDW + lane * 4;
        split2(v.x, dh[0], dl[0]);
        split2(v.y, dh[1], dl[1]);
        split2(v.z, dh[2], dl[2]);
        split2(v.w, dh[3], dl[3]);
    }

    int warpM = w & 3, warpN = w >> 2;
    int rbase = warpM * 32, cbase = warpN * 64;
    int qid = lane >> 2, tq = lane & 3;

    float acc[2][8][4];
    #pragma unroll
    for (int mi = 0; mi < 2; mi++)
        #pragma unroll
        for (int ni = 0; ni < 8; ni++)
            #pragma unroll
            for (int j = 0; j < 4; j++) acc[mi][ni][j] = 0.f;

    for (int st = 0; st < 2; st++) {
        if (st) __syncthreads();   // previous-stage reads done before overwrite
        // load + split A half-K stage (gathered rows + optional transform)
        for (int rr = w; rr < 128; rr += 8) {
            int gr = bm + rr;
            float2 v = make_float2(0.f, 0.f);
            if (gr < cnt) {
                int row = rows ? rows[gr] : gr;
                v = *(const float2*)(X + (long long)row * DD + st * 64 + lane * 2);
                if (doX) {
                    if (xform == 1) { v.x = signed_cbrt(v.x); v.y = signed_cbrt(v.y); }
                    else            { v.x = gelu_exact(v.x);  v.y = gelu_exact(v.y); }
                }
            }
            int o = rr * LDK + lane * 2;
            split2(v.x, Ahi[o],     Alo[o]);
            split2(v.y, Ahi[o + 1], Alo[o + 1]);
        }
        __syncthreads();

        #pragma unroll
        for (int ks = 0; ks < 8; ks++) {
            int kb = ks * 8;              // local A col
            int kg = st * 64 + kb;        // global W row
            unsigned ah[2][4], al[2][4];
            #pragma unroll
            for (int mi = 0; mi < 2; mi++) {
                const float* ph = Ahi + (rbase + mi * 16 + qid) * LDK + kb + tq;
                const float* pl = Alo + (rbase + mi * 16 + qid) * LDK + kb + tq;
                ah[mi][0] = __float_as_uint(ph[0]);
                ah[mi][1] = __float_as_uint(ph[8 * LDK]);
                ah[mi][2] = __float_as_uint(ph[4]);
                ah[mi][3] = __float_as_uint(ph[8 * LDK + 4]);
                al[mi][0] = __float_as_uint(pl[0]);
                al[mi][1] = __float_as_uint(pl[8 * LDK]);
                al[mi][2] = __float_as_uint(pl[4]);
                al[mi][3] = __float_as_uint(pl[8 * LDK + 4]);
            }
            #pragma unroll
            for (int ni = 0; ni < 8; ni++) {
                const float* bh = Whi + (kg + tq) * LDW + cbase + ni * 8 + qid;
                const float* bl = Wlo + (kg + tq) * LDW + cbase + ni * 8 + qid;
                unsigned bh0 = __float_as_uint(bh[0]);
                unsigned bh1 = __float_as_uint(bh[4 * LDW]);
                unsigned bl0 = __float_as_uint(bl[0]);
                unsigned bl1 = __float_as_uint(bl[4 * LDW]);
                #pragma unroll
                for (int mi = 0; mi < 2; mi++) {
                    asm volatile(
                        "mma.sync.aligned.m16n8k8.row.col.f32.tf32.tf32.f32 "
                        "{%0,%1,%2,%3}, {%4,%5,%6,%7}, {%8,%9}, {%0,%1,%2,%3};"
                        : "+f"(acc[mi][ni][0]), "+f"(acc[mi][ni][1]),
                          "+f"(acc[mi][ni][2]), "+f"(acc[mi][ni][3])
                        : "r"(ah[mi][0]), "r"(ah[mi][1]), "r"(ah[mi][2]), "r"(ah[mi][3]),
                          "r"(bh0), "r"(bh1));
                    asm volatile(
                        "mma.sync.aligned.m16n8k8.row.col.f32.tf32.tf32.f32 "
                        "{%0,%1,%2,%3}, {%4,%5,%6,%7}, {%8,%9}, {%0,%1,%2,%3};"
                        : "+f"(acc[mi][ni][0]), "+f"(acc[mi][ni][1]),
                          "+f"(acc[mi][ni][2]), "+f"(acc[mi][ni][3])
                        : "r"(al[mi][0]), "r"(al[mi][1]), "r"(al[mi][2]), "r"(al[mi][3]),
                          "r"(bh0), "r"(bh1));
                    asm volatile(
                        "mma.sync.aligned.m16n8k8.row.col.f32.tf32.tf32.f32 "
                        "{%0,%1,%2,%3}, {%4,%5,%6,%7}, {%8,%9}, {%0,%1,%2,%3};"
                        : "+f"(acc[mi][ni][0]), "+f"(acc[mi][ni][1]),
                          "+f"(acc[mi][ni][2]), "+f"(acc[mi][ni][3])
                        : "r"(ah[mi][0]), "r"(ah[mi][1]), "r"(ah[mi][2]), "r"(ah[mi][3]),
                          "r"(bl0), "r"(bl1));
                }
            }
        }
    }

    // epilogue: bias + scatter store
    #pragma unroll
    for (int ni = 0; ni < 8; ni++) {
        int col = cbase + ni * 8 + tq * 2;
        float bx = 0.f, by = 0.f;
        if (B) { bx = B[col]; by = B[col + 1]; }
        #pragma unroll
        for (int mi = 0; mi < 2; mi++) {
            int r0 = bm + rbase + mi * 16 + qid;
            if (r0 < cnt) {
                int row = rows ? rows[r0] : r0;
                float2 o = make_float2(acc[mi][ni][0] + bx, acc[mi][ni][1] + by);
                *(float2*)(C + (long long)row * DD + col) = o;
            }
            int r1 = r0 + 8;
            if (r1 < cnt) {
                int row = rows ? rows[r1] : r1;
                float2 o = make_float2(acc[mi][ni][2] + bx, acc[mi][ni][3] + by);
                *(float2*)(C + (long long)row * DD + col) = o;
            }
        }
    }
}

// ---------------- bf[k] = bq @ Wak[k] -----------------------------------------
__global__ void k_bf(const float* __restrict__ bq, const float* __restrict__ Wak) {
    int k = blockIdx.x, n = threadIdx.x;
    float s = 0.f;
    for (int d = 0; d < DD; d++) s += bq[d] * Wak[((long long)k * DD + d) * DD + n];
    g_bf[k * DD + n] = s;
}

// ---------------- qA = rel_att-transformed q, per node per relation ----------
__global__ void k_qA(const float* __restrict__ rel_att) {
    extern __shared__ float Ashm[];   // permuted: Ashm[(rh*32+m)*32+d]
    for (int i = threadIdx.x; i < RR * HH * DKK * DKK; i += blockDim.x) {
        int rh = i >> 10, dm = i & 1023, d = dm >> 5, m = dm & 31;
        Ashm[(rh * 32 + m) * 32 + d] = rel_att[i];
    }
    __syncthreads();
    int lane = threadIdx.x & 31;
    int gw = (blockIdx.x * blockDim.x + threadIdx.x) >> 5;
    int nw = (gridDim.x * blockDim.x) >> 5;
    for (int n = gw; n < NN; n += nw) {
        float qr[HH];
        #pragma unroll
        for (int h = 0; h < HH; h++) qr[h] = g_q[n * DD + h * 32 + lane];
        #pragma unroll
        for (int h = 0; h < HH; h++) {
            float a0 = 0, a1 = 0, a2 = 0, a3 = 0, a4 = 0;
            #pragma unroll
            for (int m = 0; m < 32; m++) {
                float qm = __shfl_sync(0xffffffffu, qr[h], m);
                int base = (h * 32 + m) * 32 + lane;
                a0 += Ashm[base        ] * qm;
                a1 += Ashm[base +  4096] * qm;
                a2 += Ashm[base +  8192] * qm;
                a3 += Ashm[base + 12288] * qm;
                a4 += Ashm[base + 16384] * qm;
            }
            g_qA[((n * RR + 0) * HH + h) * 32 + lane] = a0;
            g_qA[((n * RR + 1) * HH + h) * 32 + lane] = a1;
            g_qA[((n * RR + 2) * HH + h) * 32 + lane] = a2;
            g_qA[((n * RR + 3) * HH + h) * 32 + lane] = a3;
            g_qA[((n * RR + 4) * HH + h) * 32 + lane] = a4;
        }
    }
}

// ---------------- edge logits + segment max + degree ----------------
__global__ void k_logits(const int* __restrict__ ei, const int* __restrict__ et,
                         const float* __restrict__ rel_pri) {
    int lane = threadIdx.x & 31;
    int gw = (blockIdx.x * blockDim.x + threadIdx.x) >> 5;
    int nw = (gridDim.x * blockDim.x) >> 5;
    for (int e = gw; e < EE; e += nw) {
        int s = ei[e], tg = ei[EE + e], r = et[e];
        float p0, p1, p2, p3;
        {
            const float* kb = g_k + (long long)s * DD;
            const float* qa = g_qA + ((long long)tg * RR + r) * DD;
            p0 = kb[lane]      * qa[lane];
            p1 = kb[32 + lane] * qa[32 + lane];
            p2 = kb[64 + lane] * qa[64 + lane];
            p3 = kb[96 + lane] * qa[96 + lane];
        }
        p0 = warp_sum(p0); p1 = warp_sum(p1); p2 = warp_sum(p2); p3 = warp_sum(p3);
        if (lane == 0) {
            atomicAdd(&g_deg[tg], 1);
            float l0 = p0 * rel_pri[r * HH + 0] * INV_SQRT_DK;
            float l1 = p1 * rel_pri[r * HH + 1] * INV_SQRT_DK;
            float l2 = p2 * rel_pri[r * HH + 2] * INV_SQRT_DK;
            float l3 = p3 * rel_pri[r * HH + 3] * INV_SQRT_DK;
            g_logits[e * HH + 0] = l0; g_logits[e * HH + 1] = l1;
            g_logits[e * HH + 2] = l2; g_logits[e * HH + 3] = l3;
            atomicMax(&g_mx[tg * HH + 0], enc_f(l0));
            atomicMax(&g_mx[tg * HH + 1], enc_f(l1));
            atomicMax(&g_mx[tg * HH + 2], enc_f(l2));
            atomicMax(&g_mx[tg * HH + 3], enc_f(l3));
        }
    }
}

// ---------------- exp + segment sum ----------------
__global__ void k_exp(const int* __restrict__ ei) {
    int idx = blockIdx.x * blockDim.x + threadIdx.x;
    if (idx >= EE * HH) return;
    int e = idx >> 2, h = idx & 3;
    int tg = ei[EE + e];
    float ex = expf(g_logits[idx] - dec_f(g_mx[tg * HH + h]));
    g_logits[idx] = ex;
    atomicAdd(&g_sum[tg * HH + h], ex);
}

// ---------------- messages / agg for edge-index n < N ----------------
__global__ void k_msg(const float* __restrict__ rel_msg, const int* __restrict__ ei,
                      const int* __restrict__ et) {
    extern __shared__ float Ms[];
    for (int i = threadIdx.x; i < RR * HH * DKK * DKK; i += blockDim.x) Ms[i] = rel_msg[i];
    __syncthreads();
    int lane = threadIdx.x & 31;
    int gw = (blockIdx.x * blockDim.x + threadIdx.x) >> 5;
    int nw = (gridDim.x * blockDim.x) >> 5;
    for (int n = gw; n < NN; n += nw) {
        int s = ei[n], tg = ei[EE + n], r = et[n];
        float deg = (float)g_deg[n];
        float vr[HH];
        #pragma unroll
        for (int h = 0; h < HH; h++) vr[h] = g_v[(long long)s * DD + h * 32 + lane];
        #pragma unroll
        for (int h = 0; h < HH; h++) {
            float att = g_logits[n * HH + h] / (g_sum[tg * HH + h] + 1e-16f);
            float vp = 0.f;
            const float* Mb = Ms + (r * HH + h) * 1024;
            #pragma unroll
            for (int d = 0; d < 32; d++) {
                float vd = __shfl_sync(0xffffffffu, vr[h], d);
                vp += Mb[d * 32 + lane] * vd;
            }
            float base = deg * att;
            int o = n * DD + h * 32 + lane;
            float vp2 = vp * vp;
            g_agg[o]          = base * vp;
            g_agg[ND + o]     = base * vp2;
            g_agg[2 * ND + o] = base * vp2 * vp;
        }
    }
}

// ---------------- gating: res = sum_k sigmoid(front_k . tail_k) * aggm_k -----
__global__ void k_gate() {
    int w = (blockIdx.x * blockDim.x + threadIdx.x) >> 5;
    int lane = threadIdx.x & 31;
    if (w >= NN) return;
    int o = w * DD + lane * 4;
    float4 r4 = make_float4(0.f, 0.f, 0.f, 0.f);
    #pragma unroll
    for (int k = 0; k < KKM; k++) {
        float4 f = *(float4*)&g_front[k * ND + o];
        float4 t = *(float4*)&g_tail[k * ND + o];
        float p = f.x * t.x + f.y * t.y + f.z * t.z + f.w * t.w;
        p = warp_sum(p);
        float gate = 1.f / (1.f + expf(-p));
        float4 a = *(float4*)&g_aggm[k * ND + o];
        r4.x += gate * a.x; r4.y += gate * a.y; r4.z += gate * a.z; r4.w += gate * a.w;
    }
    *(float4*)&g_res[o] = r4;
}

// ---------------- skip blend + LayerNorm (after typed a_w GEMM) --------------
__global__ void k_postln(const int* __restrict__ nt, const float* __restrict__ xin,
                         const float* __restrict__ skip, const float* __restrict__ lng,
                         const float* __restrict__ lnb, float* __restrict__ out) {
    int wid = (blockIdx.x * blockDim.x + threadIdx.x) >> 5;
    int lane = threadIdx.x & 31;
    if (wid >= NN) return;
    int t = nt[wid];
    float alpha = 1.f / (1.f + expf(-skip[t]));
    int o = wid * DD + lane * 4;
    float4 tr = *(float4*)&g_trans[o];
    float4 xv = *(const float4*)(xin + o);
    float y0 = tr.x * alpha + xv.x * (1.f - alpha);
    float y1 = tr.y * alpha + xv.y * (1.f - alpha);
    float y2 = tr.z * alpha + xv.z * (1.f - alpha);
    float y3 = tr.w * alpha + xv.w * (1.f - alpha);
    float s  = y0 + y1 + y2 + y3;
    float ss = y0 * y0 + y1 * y1 + y2 * y2 + y3 * y3;
    #pragma unroll
    for (int of = 16; of > 0; of >>= 1) {
        s  += __shfl_xor_sync(0xffffffffu, s,  of);
        ss += __shfl_xor_sync(0xffffffffu, ss, of);
    }
    float mu  = s * (1.f / 128.f);
    float inv = rsqrtf(ss * (1.f / 128.f) - mu * mu + 1e-5f);
    float4 gg = *(const float4*)(lng + t * DD + lane * 4);
    float4 bb = *(const float4*)(lnb + t * DD + lane * 4);
    float4 o4;
    o4.x = (y0 - mu) * inv * gg.x + bb.x;
    o4.y = (y1 - mu) * inv * gg.y + bb.y;
    o4.z = (y2 - mu) * inv * gg.z + bb.z;
    o4.w = (y3 - mu) * inv * gg.w + bb.w;
    *(float4*)(out + (long long)wid * DD + lane * 4) = o4;
}

// ---------------- launch ----------------
extern "C" void kernel_launch(void* const* d_in, const int* in_sizes, int n_in,
                              void* d_out, int out_size) {
    const float* meta_xs  = (const float*)d_in[0];
    const int*   node_type= (const int*)  d_in[1];
    const int*   edge_idx = (const int*)  d_in[2];
    const int*   edge_type= (const int*)  d_in[3];
    const float* q_w = (const float*)d_in[5],  *q_b = (const float*)d_in[6];
    const float* k_w = (const float*)d_in[7],  *k_b = (const float*)d_in[8];
    const float* v_w = (const float*)d_in[9],  *v_b = (const float*)d_in[10];
    const float* a_w = (const float*)d_in[11], *a_b = (const float*)d_in[12];
    const float* rel_pri = (const float*)d_in[13];
    const float* rel_att = (const float*)d_in[14];
    const float* rel_msg = (const float*)d_in[15];
    const float* WMk = (const float*)d_in[16];
    const float* Wak = (const float*)d_in[17];
    const float* Wq  = (const float*)d_in[18], *bq  = (const float*)d_in[19];
    const float* Wkl = (const float*)d_in[20], *bkl = (const float*)d_in[21];
    const float* skip= (const float*)d_in[22];
    const float* lng = (const float*)d_in[23], *lnb = (const float*)d_in[24];
    float* out = (float*)d_out;

    cudaFuncSetAttribute(k_qA,    cudaFuncAttributeMaxDynamicSharedMemorySize, 81920);
    cudaFuncSetAttribute(k_msg,   cudaFuncAttributeMaxDynamicSharedMemorySize, 81920);
    cudaFuncSetAttribute(tc_gemm, cudaFuncAttributeMaxDynamicSharedMemorySize, SM_BYTES);

    void *pq, *pk, *pv, *pagg, *paggm, *pfront, *ptail, *pres, *ptrans;
    void *pWt, *pWf, *pbf;
    cudaGetSymbolAddress(&pq, g_q);
    cudaGetSymbolAddress(&pk, g_k);
    cudaGetSymbolAddress(&pv, g_v);
    cudaGetSymbolAddress(&pagg, g_agg);
    cudaGetSymbolAddress(&paggm, g_aggm);
    cudaGetSymbolAddress(&pfront, g_front);
    cudaGetSymbolAddress(&ptail, g_tail);
    cudaGetSymbolAddress(&pres, g_res);
    cudaGetSymbolAddress(&ptrans, g_trans);
    cudaGetSymbolAddress(&pWt, g_Wt);
    cudaGetSymbolAddress(&pWf, g_Wf);
    cudaGetSymbolAddress(&pbf, g_bf);

    k_init<<<512, 256>>>();
    k_count<<<(NN + 255) / 256, 256>>>(node_type);
    k_offs<<<1, 1>>>();
    k_scatter<<<(NN + 255) / 256, 256>>>(node_type);

    // weight combines: Wt[k] = WMk[k]@Wkl, Wf[k] = Wq@Wak[k], bf[k] = bq@Wak[k]
    tc_gemm<<<dim3(1, KKM), 256, SM_BYTES>>>(WMk, (long long)DD * DD, Wkl, 0,
                                             nullptr, 0, (float*)pWt, (long long)DD * DD,
                                             0, DD, 0, -1);
    tc_gemm<<<dim3(1, KKM), 256, SM_BYTES>>>(Wq, 0, Wak, (long long)DD * DD,
                                             nullptr, 0, (float*)pWf, (long long)DD * DD,
                                             0, DD, 0, -1);
    k_bf<<<KKM, 128>>>(bq, Wak);

    dim3 gT((NN + 127) / 128, TT);
    dim3 gK((NN + 127) / 128, KKM);

    // typed projections q,k,v  (tensor cores, 3xTF32)
    tc_gemm<<<gT, 256, SM_BYTES>>>(meta_xs, 0, q_w, 0, q_b, 0, (float*)pq, 0, 1, 0, 0, -1);
    tc_gemm<<<gT, 256, SM_BYTES>>>(meta_xs, 0, k_w, 0, k_b, 0, (float*)pk, 0, 1, 0, 0, -1);
    tc_gemm<<<gT, 256, SM_BYTES>>>(meta_xs, 0, v_w, 0, v_b, 0, (float*)pv, 0, 1, 0, 0, -1);

    // qA precompute, edge logits, softmax, messages
    k_qA<<<592, 256, 81920>>>(rel_att);
    k_logits<<<2368, 256>>>(edge_idx, edge_type, rel_pri);
    k_exp<<<(EE * HH + 255) / 256, 256>>>(edge_idx);
    k_msg<<<592, 256, 81920>>>(rel_msg, edge_idx, edge_type);

    // aggm[k] = root_if_last(agg[k]) @ WMk[k]
    tc_gemm<<<gK, 256, SM_BYTES>>>((const float*)pagg, ND, WMk, (long long)DD * DD,
                                   nullptr, 0, (float*)paggm, ND, 0, NN, 1, KKM - 1);
    // tail[k] = root_if_last(agg[k]) @ Wt[k] + bkl   (fused aggm@Wkl)
    tc_gemm<<<gK, 256, SM_BYTES>>>((const float*)pagg, ND, (const float*)pWt,
                                   (long long)DD * DD, bkl, 0,
                                   (float*)ptail, ND, 0, NN, 1, KKM - 1);
    // front[k] = x @ Wf[k] + bf[k]   (fused qlin@Wak)
    tc_gemm<<<gK, 256, SM_BYTES>>>(meta_xs, 0, (const float*)pWf, (long long)DD * DD,
                                   (const float*)pbf, DD,
                                   (float*)pfront, ND, 0, NN, 0, -1);

    // gating -> res
    k_gate<<<(NN * 32 + 255) / 256, 256>>>();

    // trans = typed a_w GEMM over gelu(res)
    tc_gemm<<<gT, 256, SM_BYTES>>>((const float*)pres, 0, a_w, 0, a_b, 0,
                                   (float*)ptrans, 0, 1, 0, 2, -2);
    // skip blend + LayerNorm
    k_postln<<<(NN * 32 + 255) / 256, 256>>>(node_type, meta_xs, skip, lng, lnb, out);
}

// round 6
// speedup vs baseline: 1.8110x; 1.8110x over previous
#include <cuda_runtime.h>
#include <cuda_fp16.h>
#include <math.h>
#include <stdint.h>

#define NN 40000
#define EE 320000
#define DD 128
#define HH 4
#define TT 3
#define RR 5
#define KKM 3
#define DKK 32
#define ND (NN*DD)
#define INV_SQRT_DK 0.17677669529663687f   // 1/sqrt(32)

// smem layout for fp16-split GEMM (bytes). A planes: 128 rows x 72 halves
// (144B pitch). B planes: 64 k-rows x 136 halves (272B pitch).
#define OFF_AH 0
#define OFF_AL (128*144)
#define OFF_BH (2*128*144)
#define OFF_BL (2*128*144 + 64*272)
#define OFF_BIAS (2*128*144 + 2*64*272)
#define GSM_BYTES (OFF_BIAS + 512)

// ---------------- scratch (device globals; no allocation allowed) -------------
__device__ float    g_q[ND];
__device__ float    g_k[ND];
__device__ float    g_v[ND];
__device__ float    g_qA[NN*RR*DD];
__device__ float    g_logits[EE*HH];     // logits, then exp() in place
__device__ unsigned g_mx[NN*HH];         // encoded float max
__device__ float    g_sum[NN*HH];
__device__ int      g_deg[NN];
__device__ float    g_agg[KKM*ND];
__device__ float    g_aggm[KKM*ND];
__device__ float    g_front[KKM*ND];
__device__ float    g_tail[KKM*ND];
__device__ float    g_res[ND];
__device__ float    g_trans[ND];
__device__ float    g_Wt[KKM*DD*DD];     // WMk[k] @ Wkl
__device__ float    g_Wf[KKM*DD*DD];     // Wq @ Wak[k]
__device__ float    g_bf[KKM*DD];        // bq @ Wak[k]
__device__ int      g_list[NN];
__device__ int      g_cnt[TT];
__device__ int      g_off[TT];
__device__ int      g_cur[TT];

// ---------------- helpers ----------------
__device__ __forceinline__ unsigned enc_f(float f) {
    unsigned u = __float_as_uint(f);
    return (u & 0x80000000u) ? ~u : (u | 0x80000000u);
}
__device__ __forceinline__ float dec_f(unsigned u) {
    return (u & 0x80000000u) ? __uint_as_float(u & 0x7fffffffu) : __uint_as_float(~u);
}
__device__ __forceinline__ float signed_cbrt(float a) {
    float s = (a > 0.f) ? 1.f : ((a < 0.f) ? -1.f : 0.f);
    return s * cbrtf(fabsf(a) + 1e-18f);
}
__device__ __forceinline__ float gelu_exact(float x) {
    return 0.5f * x * (1.f + erff(x * 0.70710678118654752440f));
}
__device__ __forceinline__ float warp_sum(float p) {
    #pragma unroll
    for (int o = 16; o > 0; o >>= 1) p += __shfl_xor_sync(0xffffffffu, p, o);
    return p;
}
// split x into fp16 hi + fp16 lo (x ≈ hi + lo, dropped term ~2^-22 rel)
__device__ __forceinline__ void splith(float x, __half& hi, __half& lo) {
    __half h = __float2half_rn(x);
    hi = h;
    lo = __float2half_rn(x - __half2float(h));
}
__device__ __forceinline__ uint32_t smem_u32(const void* p) {
    uint32_t a;
    asm("{ .reg .u64 t; cvta.to.shared.u64 t, %1; cvt.u32.u64 %0, t; }" : "=r"(a) : "l"(p));
    return a;
}

#define LDSM4(r, addr)                                                        \
    asm volatile("ldmatrix.sync.aligned.m8n8.x4.shared.b16 {%0,%1,%2,%3}, [%4];" \
        : "=r"((r)[0]), "=r"((r)[1]), "=r"((r)[2]), "=r"((r)[3]) : "r"(addr))
#define LDSM4T(r, addr)                                                       \
    asm volatile("ldmatrix.sync.aligned.m8n8.x4.trans.shared.b16 {%0,%1,%2,%3}, [%4];" \
        : "=r"((r)[0]), "=r"((r)[1]), "=r"((r)[2]), "=r"((r)[3]) : "r"(addr))
#define MMA16(acc, a, b0, b1)                                                 \
    asm volatile("mma.sync.aligned.m16n8k16.row.col.f32.f16.f16.f32 "         \
        "{%0,%1,%2,%3}, {%4,%5,%6,%7}, {%8,%9}, {%0,%1,%2,%3};"               \
        : "+f"((acc)[0]), "+f"((acc)[1]), "+f"((acc)[2]), "+f"((acc)[3])      \
        : "r"((a)[0]), "r"((a)[1]), "r"((a)[2]), "r"((a)[3]), "r"(b0), "r"(b1))

// ---------------- init / bucketing ----------------
__global__ void k_init() {
    int i = blockIdx.x * blockDim.x + threadIdx.x;
    int stride = gridDim.x * blockDim.x;
    for (int j = i; j < NN * HH; j += stride) { g_mx[j] = 0u; g_sum[j] = 0.f; }
    for (int j = i; j < NN; j += stride) g_deg[j] = 0;
    if (i < TT) { g_cnt[i] = 0; g_cur[i] = 0; }
}
__global__ void k_count(const int* __restrict__ nt) {
    int n = blockIdx.x * blockDim.x + threadIdx.x;
    if (n < NN) atomicAdd(&g_cnt[nt[n]], 1);
}
__global__ void k_offs() {
    int o = 0;
    for (int t = 0; t < TT; t++) { g_off[t] = o; g_cur[t] = o; o += g_cnt[t]; }
}
__global__ void k_scatter(const int* __restrict__ nt) {
    int n = blockIdx.x * blockDim.x + threadIdx.x;
    if (n < NN) {
        int p = atomicAdd(&g_cur[nt[n]], 1);
        g_list[p] = n;
    }
}

// ------ fp16-split tensor GEMM: C[rows] = xform(X[rows]) @ W + B -------------
// 128x128 tile, K=128 staged in 2 chunks of 64. 8 warps (4M x 2N).
// acc += Ahi*Whi + Alo*Whi + Ahi*Wlo  (fp32 accumulate; drops lo*lo ~2^-22).
__global__ __launch_bounds__(256, 2) void tc_gemm(
    const float* __restrict__ X, long long xs,
    const float* __restrict__ W, long long ws,
    const float* __restrict__ B, long long bs,
    float* __restrict__ C, long long cs,
    int typed, int nrows, int xform, int xform_gy)
{
    extern __shared__ char smc[];
    __half* Ah = (__half*)(smc + OFF_AH);
    __half* Al = (__half*)(smc + OFF_AL);
    __half* Bh = (__half*)(smc + OFF_BH);
    __half* Bl = (__half*)(smc + OFF_BL);
    float* biasp = (float*)(smc + OFF_BIAS);

    int gy = blockIdx.y;
    const int* rows = nullptr;
    int cnt;
    if (typed) {
        rows = g_list + g_off[gy];
        cnt = g_cnt[gy];
        W += (long long)gy * DD * DD;
        if (B) B += (long long)gy * DD;
    } else {
        X += (long long)gy * xs;
        W += (long long)gy * ws;
        if (B) B += (long long)gy * bs;
        C += (long long)gy * cs;
        cnt = nrows;
    }
    int bm = blockIdx.x * 128;
    if (bm >= cnt) return;
    bool doX = xform && (xform_gy == -2 || gy == xform_gy);

    int tid = threadIdx.x, wid = tid >> 5, lane = tid & 31;
    if (tid < 128) biasp[tid] = B ? B[tid] : 0.f;

    int warpM = wid & 3, warpN = wid >> 2;
    int rbase = warpM * 32, cbase = warpN * 64;
    int qid = lane >> 2, tq = lane & 3;

    // ldmatrix per-lane address components
    int li = lane & 7, ls = lane >> 3;
    int a_row = li + ((ls & 1) << 3);          // + tile row
    int a_col = ((ls >> 1) & 1) << 3;          // halves
    int b_krow = li + ((ls >> 1) << 3);
    int b_ncol = (ls & 1) << 3;

    uint32_t uAh = smem_u32(Ah), uAl = smem_u32(Al);
    uint32_t uBh = smem_u32(Bh), uBl = smem_u32(Bl);
    uint32_t aoff = (uint32_t)(rbase + a_row) * 144u + (uint32_t)a_col * 2u;
    uint32_t boff = (uint32_t)b_krow * 272u + (uint32_t)(cbase + b_ncol) * 2u;

    float acc[2][8][4];
    #pragma unroll
    for (int mi = 0; mi < 2; mi++)
        #pragma unroll
        for (int ni = 0; ni < 8; ni++)
            #pragma unroll
            for (int j = 0; j < 4; j++) acc[mi][ni][j] = 0.f;

    for (int stage = 0; stage < 2; stage++) {
        if (stage) __syncthreads();
        // stage A: 128 rows x 64 cols (gather + xform + split)
        for (int s = tid; s < 2048; s += 256) {
            int r = s >> 4, c = (s & 15) << 2;
            float4 v = make_float4(0.f, 0.f, 0.f, 0.f);
            int gr = bm + r;
            if (gr < cnt) {
                int row = rows ? rows[gr] : gr;
                v = *(const float4*)(X + (long long)row * DD + stage * 64 + c);
                if (doX) {
                    if (xform == 1) {
                        v.x = signed_cbrt(v.x); v.y = signed_cbrt(v.y);
                        v.z = signed_cbrt(v.z); v.w = signed_cbrt(v.w);
                    } else {
                        v.x = gelu_exact(v.x); v.y = gelu_exact(v.y);
                        v.z = gelu_exact(v.z); v.w = gelu_exact(v.w);
                    }
                }
            }
            __half h0, h1, h2, h3, l0, l1, l2, l3;
            splith(v.x, h0, l0); splith(v.y, h1, l1);
            splith(v.z, h2, l2); splith(v.w, h3, l3);
            int o = r * 72 + c;
            *(__half2*)(Ah + o)     = __halves2half2(h0, h1);
            *(__half2*)(Ah + o + 2) = __halves2half2(h2, h3);
            *(__half2*)(Al + o)     = __halves2half2(l0, l1);
            *(__half2*)(Al + o + 2) = __halves2half2(l2, l3);
        }
        // stage B: 64 k-rows x 128 n  (gmem layout preserved)
        for (int s = tid; s < 2048; s += 256) {
            int k = s >> 5, c = (s & 31) << 2;
            float4 v = *(const float4*)(W + (long long)(stage * 64 + k) * DD + c);
            __half h0, h1, h2, h3, l0, l1, l2, l3;
            splith(v.x, h0, l0); splith(v.y, h1, l1);
            splith(v.z, h2, l2); splith(v.w, h3, l3);
            int o = k * 136 + c;
            *(__half2*)(Bh + o)     = __halves2half2(h0, h1);
            *(__half2*)(Bh + o + 2) = __halves2half2(h2, h3);
            *(__half2*)(Bl + o)     = __halves2half2(l0, l1);
            *(__half2*)(Bl + o + 2) = __halves2half2(l2, l3);
        }
        __syncthreads();

        #pragma unroll
        for (int ks = 0; ks < 4; ks++) {
            uint32_t ka = aoff + (uint32_t)ks * 32u;
            uint32_t ah[2][4], al[2][4];
            LDSM4(ah[0], uAh + ka);
            LDSM4(ah[1], uAh + ka + 16u * 144u);
            LDSM4(al[0], uAl + ka);
            LDSM4(al[1], uAl + ka + 16u * 144u);
            #pragma unroll
            for (int nf = 0; nf < 4; nf++) {
                uint32_t kb = boff + (uint32_t)ks * 4352u + (uint32_t)nf * 32u;
                uint32_t bhf[4], blf[4];
                LDSM4T(bhf, uBh + kb);
                LDSM4T(blf, uBl + kb);
                #pragma unroll
                for (int j = 0; j < 2; j++) {
                    #pragma unroll
                    for (int mi = 0; mi < 2; mi++) {
                        float* a4 = acc[mi][nf * 2 + j];
                        MMA16(a4, ah[mi], bhf[j], bhf[2 + j]);
                        MMA16(a4, al[mi], bhf[j], bhf[2 + j]);
                        MMA16(a4, ah[mi], blf[j], blf[2 + j]);
                    }
                }
            }
        }
    }

    // epilogue: bias + scatter store
    #pragma unroll
    for (int ni = 0; ni < 8; ni++) {
        int col = cbase + ni * 8 + tq * 2;
        float bx = biasp[col], by = biasp[col + 1];
        #pragma unroll
        for (int mi = 0; mi < 2; mi++) {
            int r0 = bm + rbase + mi * 16 + qid;
            if (r0 < cnt) {
                int row = rows ? rows[r0] : r0;
                float2 o = make_float2(acc[mi][ni][0] + bx, acc[mi][ni][1] + by);
                *(float2*)(C + (long long)row * DD + col) = o;
            }
            int r1 = r0 + 8;
            if (r1 < cnt) {
                int row = rows ? rows[r1] : r1;
                float2 o = make_float2(acc[mi][ni][2] + bx, acc[mi][ni][3] + by);
                *(float2*)(C + (long long)row * DD + col) = o;
            }
        }
    }
}

// ---------------- bf[k] = bq @ Wak[k] -----------------------------------------
__global__ void k_bf(const float* __restrict__ bq, const float* __restrict__ Wak) {
    int k = blockIdx.x, n = threadIdx.x;
    float s = 0.f;
    for (int d = 0; d < DD; d++) s += bq[d] * Wak[((long long)k * DD + d) * DD + n];
    g_bf[k * DD + n] = s;
}

// ---------------- qA = rel_att-transformed q, per node per relation ----------
__global__ void k_qA(const float* __restrict__ rel_att) {
    extern __shared__ float Ashm[];   // permuted: Ashm[(rh*32+m)*32+d]
    for (int i = threadIdx.x; i < RR * HH * DKK * DKK; i += blockDim.x) {
        int rh = i >> 10, dm = i & 1023, d = dm >> 5, m = dm & 31;
        Ashm[(rh * 32 + m) * 32 + d] = rel_att[i];
    }
    __syncthreads();
    int lane = threadIdx.x & 31;
    int gw = (blockIdx.x * blockDim.x + threadIdx.x) >> 5;
    int nw = (gridDim.x * blockDim.x) >> 5;
    for (int n = gw; n < NN; n += nw) {
        float qr[HH];
        #pragma unroll
        for (int h = 0; h < HH; h++) qr[h] = g_q[n * DD + h * 32 + lane];
        #pragma unroll
        for (int h = 0; h < HH; h++) {
            float a0 = 0, a1 = 0, a2 = 0, a3 = 0, a4 = 0;
            #pragma unroll
            for (int m = 0; m < 32; m++) {
                float qm = __shfl_sync(0xffffffffu, qr[h], m);
                int base = (h * 32 + m) * 32 + lane;
                a0 += Ashm[base        ] * qm;
                a1 += Ashm[base +  4096] * qm;
                a2 += Ashm[base +  8192] * qm;
                a3 += Ashm[base + 12288] * qm;
                a4 += Ashm[base + 16384] * qm;
            }
            g_qA[((n * RR + 0) * HH + h) * 32 + lane] = a0;
            g_qA[((n * RR + 1) * HH + h) * 32 + lane] = a1;
            g_qA[((n * RR + 2) * HH + h) * 32 + lane] = a2;
            g_qA[((n * RR + 3) * HH + h) * 32 + lane] = a3;
            g_qA[((n * RR + 4) * HH + h) * 32 + lane] = a4;
        }
    }
}

// ---------------- edge logits + segment max + degree ----------------
__global__ void k_logits(const int* __restrict__ ei, const int* __restrict__ et,
                         const float* __restrict__ rel_pri) {
    int lane = threadIdx.x & 31;
    int gw = (blockIdx.x * blockDim.x + threadIdx.x) >> 5;
    int nw = (gridDim.x * blockDim.x) >> 5;
    for (int e = gw; e < EE; e += nw) {
        int s = ei[e], tg = ei[EE + e], r = et[e];
        float p0, p1, p2, p3;
        {
            const float* kb = g_k + (long long)s * DD;
            const float* qa = g_qA + ((long long)tg * RR + r) * DD;
            p0 = kb[lane]      * qa[lane];
            p1 = kb[32 + lane] * qa[32 + lane];
            p2 = kb[64 + lane] * qa[64 + lane];
            p3 = kb[96 + lane] * qa[96 + lane];
        }
        p0 = warp_sum(p0); p1 = warp_sum(p1); p2 = warp_sum(p2); p3 = warp_sum(p3);
        if (lane == 0) {
            atomicAdd(&g_deg[tg], 1);
            float l0 = p0 * rel_pri[r * HH + 0] * INV_SQRT_DK;
            float l1 = p1 * rel_pri[r * HH + 1] * INV_SQRT_DK;
            float l2 = p2 * rel_pri[r * HH + 2] * INV_SQRT_DK;
            float l3 = p3 * rel_pri[r * HH + 3] * INV_SQRT_DK;
            g_logits[e * HH + 0] = l0; g_logits[e * HH + 1] = l1;
            g_logits[e * HH + 2] = l2; g_logits[e * HH + 3] = l3;
            atomicMax(&g_mx[tg * HH + 0], enc_f(l0));
            atomicMax(&g_mx[tg * HH + 1], enc_f(l1));
            atomicMax(&g_mx[tg * HH + 2], enc_f(l2));
            atomicMax(&g_mx[tg * HH + 3], enc_f(l3));
        }
    }
}

// ---------------- exp + segment sum ----------------
__global__ void k_exp(const int* __restrict__ ei) {
    int idx = blockIdx.x * blockDim.x + threadIdx.x;
    if (idx >= EE * HH) return;
    int e = idx >> 2, h = idx & 3;
    int tg = ei[EE + e];
    float ex = expf(g_logits[idx] - dec_f(g_mx[tg * HH + h]));
    g_logits[idx] = ex;
    atomicAdd(&g_sum[tg * HH + h], ex);
}

// ---------------- messages / agg for edge-index n < N ----------------
__global__ void k_msg(const float* __restrict__ rel_msg, const int* __restrict__ ei,
                      const int* __restrict__ et) {
    extern __shared__ float Ms[];
    for (int i = threadIdx.x; i < RR * HH * DKK * DKK; i += blockDim.x) Ms[i] = rel_msg[i];
    __syncthreads();
    int lane = threadIdx.x & 31;
    int gw = (blockIdx.x * blockDim.x + threadIdx.x) >> 5;
    int nw = (gridDim.x * blockDim.x) >> 5;
    for (int n = gw; n < NN; n += nw) {
        int s = ei[n], tg = ei[EE + n], r = et[n];
        float deg = (float)g_deg[n];
        float vr[HH];
        #pragma unroll
        for (int h = 0; h < HH; h++) vr[h] = g_v[(long long)s * DD + h * 32 + lane];
        #pragma unroll
        for (int h = 0; h < HH; h++) {
            float att = g_logits[n * HH + h] / (g_sum[tg * HH + h] + 1e-16f);
            float vp = 0.f;
            const float* Mb = Ms + (r * HH + h) * 1024;
            #pragma unroll
            for (int d = 0; d < 32; d++) {
                float vd = __shfl_sync(0xffffffffu, vr[h], d);
                vp += Mb[d * 32 + lane] * vd;
            }
            float base = deg * att;
            int o = n * DD + h * 32 + lane;
            float vp2 = vp * vp;
            g_agg[o]          = base * vp;
            g_agg[ND + o]     = base * vp2;
            g_agg[2 * ND + o] = base * vp2 * vp;
        }
    }
}

// ---------------- gating: res = sum_k sigmoid(front_k . tail_k) * aggm_k -----
__global__ void k_gate() {
    int w = (blockIdx.x * blockDim.x + threadIdx.x) >> 5;
    int lane = threadIdx.x & 31;
    if (w >= NN) return;
    int o = w * DD + lane * 4;
    float4 r4 = make_float4(0.f, 0.f, 0.f, 0.f);
    #pragma unroll
    for (int k = 0; k < KKM; k++) {
        float4 f = *(float4*)&g_front[k * ND + o];
        float4 t = *(float4*)&g_tail[k * ND + o];
        float p = f.x * t.x + f.y * t.y + f.z * t.z + f.w * t.w;
        p = warp_sum(p);
        float gate = 1.f / (1.f + expf(-p));
        float4 a = *(float4*)&g_aggm[k * ND + o];
        r4.x += gate * a.x; r4.y += gate * a.y; r4.z += gate * a.z; r4.w += gate * a.w;
    }
    *(float4*)&g_res[o] = r4;
}

// ---------------- skip blend + LayerNorm (after typed a_w GEMM) --------------
__global__ void k_postln(const int* __restrict__ nt, const float* __restrict__ xin,
                         const float* __restrict__ skip, const float* __restrict__ lng,
                         const float* __restrict__ lnb, float* __restrict__ out) {
    int wid = (blockIdx.x * blockDim.x + threadIdx.x) >> 5;
    int lane = threadIdx.x & 31;
    if (wid >= NN) return;
    int t = nt[wid];
    float alpha = 1.f / (1.f + expf(-skip[t]));
    int o = wid * DD + lane * 4;
    float4 tr = *(float4*)&g_trans[o];
    float4 xv = *(const float4*)(xin + o);
    float y0 = tr.x * alpha + xv.x * (1.f - alpha);
    float y1 = tr.y * alpha + xv.y * (1.f - alpha);
    float y2 = tr.z * alpha + xv.z * (1.f - alpha);
    float y3 = tr.w * alpha + xv.w * (1.f - alpha);
    float s  = y0 + y1 + y2 + y3;
    float ss = y0 * y0 + y1 * y1 + y2 * y2 + y3 * y3;
    #pragma unroll
    for (int of = 16; of > 0; of >>= 1) {
        s  += __shfl_xor_sync(0xffffffffu, s,  of);
        ss += __shfl_xor_sync(0xffffffffu, ss, of);
    }
    float mu  = s * (1.f / 128.f);
    float inv = rsqrtf(ss * (1.f / 128.f) - mu * mu + 1e-5f);
    float4 gg = *(const float4*)(lng + t * DD + lane * 4);
    float4 bb = *(const float4*)(lnb + t * DD + lane * 4);
    float4 o4;
    o4.x = (y0 - mu) * inv * gg.x + bb.x;
    o4.y = (y1 - mu) * inv * gg.y + bb.y;
    o4.z = (y2 - mu) * inv * gg.z + bb.z;
    o4.w = (y3 - mu) * inv * gg.w + bb.w;
    *(float4*)(out + (long long)wid * DD + lane * 4) = o4;
}

// ---------------- launch ----------------
extern "C" void kernel_launch(void* const* d_in, const int* in_sizes, int n_in,
                              void* d_out, int out_size) {
    const float* meta_xs  = (const float*)d_in[0];
    const int*   node_type= (const int*)  d_in[1];
    const int*   edge_idx = (const int*)  d_in[2];
    const int*   edge_type= (const int*)  d_in[3];
    const float* q_w = (const float*)d_in[5],  *q_b = (const float*)d_in[6];
    const float* k_w = (const float*)d_in[7],  *k_b = (const float*)d_in[8];
    const float* v_w = (const float*)d_in[9],  *v_b = (const float*)d_in[10];
    const float* a_w = (const float*)d_in[11], *a_b = (const float*)d_in[12];
    const float* rel_pri = (const float*)d_in[13];
    const float* rel_att = (const float*)d_in[14];
    const float* rel_msg = (const float*)d_in[15];
    const float* WMk = (const float*)d_in[16];
    const float* Wak = (const float*)d_in[17];
    const float* Wq  = (const float*)d_in[18], *bq  = (const float*)d_in[19];
    const float* Wkl = (const float*)d_in[20], *bkl = (const float*)d_in[21];
    const float* skip= (const float*)d_in[22];
    const float* lng = (const float*)d_in[23], *lnb = (const float*)d_in[24];
    float* out = (float*)d_out;

    cudaFuncSetAttribute(k_qA,    cudaFuncAttributeMaxDynamicSharedMemorySize, 81920);
    cudaFuncSetAttribute(k_msg,   cudaFuncAttributeMaxDynamicSharedMemorySize, 81920);
    cudaFuncSetAttribute(tc_gemm, cudaFuncAttributeMaxDynamicSharedMemorySize, GSM_BYTES);

    void *pq, *pk, *pv, *pagg, *paggm, *pfront, *ptail, *pres, *ptrans;
    void *pWt, *pWf, *pbf;
    cudaGetSymbolAddress(&pq, g_q);
    cudaGetSymbolAddress(&pk, g_k);
    cudaGetSymbolAddress(&pv, g_v);
    cudaGetSymbolAddress(&pagg, g_agg);
    cudaGetSymbolAddress(&paggm, g_aggm);
    cudaGetSymbolAddress(&pfront, g_front);
    cudaGetSymbolAddress(&ptail, g_tail);
    cudaGetSymbolAddress(&pres, g_res);
    cudaGetSymbolAddress(&ptrans, g_trans);
    cudaGetSymbolAddress(&pWt, g_Wt);
    cudaGetSymbolAddress(&pWf, g_Wf);
    cudaGetSymbolAddress(&pbf, g_bf);

    k_init<<<512, 256>>>();
    k_count<<<(NN + 255) / 256, 256>>>(node_type);
    k_offs<<<1, 1>>>();
    k_scatter<<<(NN + 255) / 256, 256>>>(node_type);

    // weight combines: Wt[k] = WMk[k]@Wkl, Wf[k] = Wq@Wak[k], bf[k] = bq@Wak[k]
    tc_gemm<<<dim3(1, KKM), 256, GSM_BYTES>>>(WMk, (long long)DD * DD, Wkl, 0,
                                              nullptr, 0, (float*)pWt, (long long)DD * DD,
                                              0, DD, 0, -1);
    tc_gemm<<<dim3(1, KKM), 256, GSM_BYTES>>>(Wq, 0, Wak, (long long)DD * DD,
                                              nullptr, 0, (float*)pWf, (long long)DD * DD,
                                              0, DD, 0, -1);
    k_bf<<<KKM, 128>>>(bq, Wak);

    dim3 gT((NN + 127) / 128, TT);
    dim3 gK((NN + 127) / 128, KKM);

    // typed projections q,k,v  (fp16-split tensor)
    tc_gemm<<<gT, 256, GSM_BYTES>>>(meta_xs, 0, q_w, 0, q_b, 0, (float*)pq, 0, 1, 0, 0, -1);
    tc_gemm<<<gT, 256, GSM_BYTES>>>(meta_xs, 0, k_w, 0, k_b, 0, (float*)pk, 0, 1, 0, 0, -1);
    tc_gemm<<<gT, 256, GSM_BYTES>>>(meta_xs, 0, v_w, 0, v_b, 0, (float*)pv, 0, 1, 0, 0, -1);

    // qA precompute, edge logits, softmax, messages
    k_qA<<<592, 256, 81920>>>(rel_att);
    k_logits<<<2368, 256>>>(edge_idx, edge_type, rel_pri);
    k_exp<<<(EE * HH + 255) / 256, 256>>>(edge_idx);
    k_msg<<<592, 256, 81920>>>(rel_msg, edge_idx, edge_type);

    // aggm[k] = root_if_last(agg[k]) @ WMk[k]
    tc_gemm<<<gK, 256, GSM_BYTES>>>((const float*)pagg, ND, WMk, (long long)DD * DD,
                                    nullptr, 0, (float*)paggm, ND, 0, NN, 1, KKM - 1);
    // tail[k] = root_if_last(agg[k]) @ Wt[k] + bkl   (fused aggm@Wkl)
    tc_gemm<<<gK, 256, GSM_BYTES>>>((const float*)pagg, ND, (const float*)pWt,
                                    (long long)DD * DD, bkl, 0,
                                    (float*)ptail, ND, 0, NN, 1, KKM - 1);
    // front[k] = x @ Wf[k] + bf[k]   (fused qlin@Wak)
    tc_gemm<<<gK, 256, GSM_BYTES>>>(meta_xs, 0, (const float*)pWf, (long long)DD * DD,
                                    (const float*)pbf, DD,
                                    (float*)pfront, ND, 0, NN, 0, -1);

    // gating -> res
    k_gate<<<(NN * 32 + 255) / 256, 256>>>();

    // trans = typed a_w GEMM over gelu(res)
    tc_gemm<<<gT, 256, GSM_BYTES>>>((const float*)pres, 0, a_w, 0, a_b, 0,
                                    (float*)ptrans, 0, 1, 0, 2, -2);
    // skip blend + LayerNorm
    k_postln<<<(NN * 32 + 255) / 256, 256>>>(node_type, meta_xs, skip, lng, lnb, out);
}

// round 8
// speedup vs baseline: 2.0862x; 1.1519x over previous
#include <cuda_runtime.h>
#include <cuda_fp16.h>
#include <math.h>
#include <stdint.h>

#define NN 40000
#define EE 320000
#define DD 128
#define HH 4
#define TT 3
#define RR 5
#define KKM 3
#define DKK 32
#define ND (NN*DD)
#define INV_SQRT_DK 0.17677669529663687f   // 1/sqrt(32)

// GEMM smem layout (bytes): A planes 128 rows x 176B pitch, B planes 64 x 272B
#define O2_AH 0
#define O2_AL 22528
#define O2_BH 45056
#define O2_BL 62464
#define O2_BIAS 79872
#define GSM2 80384

// ---------------- scratch (device globals; no allocation allowed) -------------
__device__ float    g_q[ND];
__device__ float    g_k[ND];
__device__ float    g_v[ND];
__device__ float    g_qA[NN*RR*DD];
__device__ float    g_logits[EE*HH];
__device__ unsigned g_mx[NN*HH];
__device__ float    g_sum[NN*HH];
__device__ int      g_deg[NN];
__device__ float    g_aggm[KKM*ND];
__device__ float    g_front[KKM*ND];
__device__ float    g_tail[KKM*ND];
__device__ float    g_trans[ND];
__device__ float    g_Wt[KKM*DD*DD];     // WMk[k] @ Wkl (fp32 exact)
__device__ float    g_Wf[KKM*DD*DD];     // Wq @ Wak[k]  (fp32 exact)
__device__ float    g_bf[KKM*DD];        // bq @ Wak[k]
// presplit half planes
__device__ __half   g_xh[ND],        g_xl[ND];          // split(meta_xs)
__device__ __half   g_aggh[KKM*ND],  g_aggl[KKM*ND];    // split(xform(agg))
__device__ __half   g_resh[ND],      g_resl[ND];        // split(gelu(res))
__device__ __half   g_wh[21*DD*DD],  g_wl[21*DD*DD];    // 21 weight matrices
__device__ int      g_list[NN];
__device__ int      g_cnt[TT];
__device__ int      g_off[TT];
__device__ int      g_cur[TT];

// ---------------- helpers ----------------
__device__ __forceinline__ unsigned enc_f(float f) {
    unsigned u = __float_as_uint(f);
    return (u & 0x80000000u) ? ~u : (u | 0x80000000u);
}
__device__ __forceinline__ float dec_f(unsigned u) {
    return (u & 0x80000000u) ? __uint_as_float(u & 0x7fffffffu) : __uint_as_float(~u);
}
__device__ __forceinline__ float signed_cbrt(float a) {
    float s = (a > 0.f) ? 1.f : ((a < 0.f) ? -1.f : 0.f);
    return s * cbrtf(fabsf(a) + 1e-18f);
}
__device__ __forceinline__ float gelu_exact(float x) {
    return 0.5f * x * (1.f + erff(x * 0.70710678118654752440f));
}
__device__ __forceinline__ float warp_sum(float p) {
    #pragma unroll
    for (int o = 16; o > 0; o >>= 1) p += __shfl_xor_sync(0xffffffffu, p, o);
    return p;
}
__device__ __forceinline__ void splith(float x, __half& hi, __half& lo) {
    __half h = __float2half_rn(x);
    hi = h;
    lo = __float2half_rn(x - __half2float(h));
}
__device__ __forceinline__ uint32_t smem_u32(const void* p) {
    uint32_t a;
    asm("{ .reg .u64 t; cvta.to.shared.u64 t, %1; cvt.u32.u64 %0, t; }" : "=r"(a) : "l"(p));
    return a;
}

#define CPA16(dst, src, sz)                                                   \
    asm volatile("cp.async.ca.shared.global [%0], [%1], 16, %2;"              \
        :: "r"(dst), "l"(src), "r"(sz))
#define CPA_WAIT()                                                            \
    do { asm volatile("cp.async.commit_group;" ::: "memory");                 \
         asm volatile("cp.async.wait_group 0;" ::: "memory"); } while (0)
#define LDSM4(r, addr)                                                        \
    asm volatile("ldmatrix.sync.aligned.m8n8.x4.shared.b16 {%0,%1,%2,%3}, [%4];" \
        : "=r"((r)[0]), "=r"((r)[1]), "=r"((r)[2]), "=r"((r)[3]) : "r"(addr))
#define LDSM4T(r, addr)                                                       \
    asm volatile("ldmatrix.sync.aligned.m8n8.x4.trans.shared.b16 {%0,%1,%2,%3}, [%4];" \
        : "=r"((r)[0]), "=r"((r)[1]), "=r"((r)[2]), "=r"((r)[3]) : "r"(addr))
#define MMA16(acc, a, b0, b1)                                                 \
    asm volatile("mma.sync.aligned.m16n8k16.row.col.f32.f16.f16.f32 "         \
        "{%0,%1,%2,%3}, {%4,%5,%6,%7}, {%8,%9}, {%0,%1,%2,%3};"               \
        : "+f"((acc)[0]), "+f"((acc)[1]), "+f"((acc)[2]), "+f"((acc)[3])      \
        : "r"((a)[0]), "r"((a)[1]), "r"((a)[2]), "r"((a)[3]), "r"(b0), "r"(b1))

// ---------------- init / bucketing ----------------
__global__ void k_init() {
    int i = blockIdx.x * blockDim.x + threadIdx.x;
    int stride = gridDim.x * blockDim.x;
    for (int j = i; j < NN * HH; j += stride) { g_mx[j] = 0u; g_sum[j] = 0.f; }
    for (int j = i; j < NN; j += stride) g_deg[j] = 0;
    if (i < TT) { g_cnt[i] = 0; g_cur[i] = 0; }
}
__global__ void k_count(const int* __restrict__ nt) {
    __shared__ int h[TT];
    if (threadIdx.x < TT) h[threadIdx.x] = 0;
    __syncthreads();
    int n = blockIdx.x * blockDim.x + threadIdx.x;
    if (n < NN) atomicAdd(&h[nt[n]], 1);
    __syncthreads();
    if (threadIdx.x < TT && h[threadIdx.x]) atomicAdd(&g_cnt[threadIdx.x], h[threadIdx.x]);
}
__global__ void k_offs() {
    int o = 0;
    for (int t = 0; t < TT; t++) { g_off[t] = o; g_cur[t] = o; o += g_cnt[t]; }
}
__global__ void k_scatter(const int* __restrict__ nt) {
    __shared__ int h[TT], base[TT];
    if (threadIdx.x < TT) h[threadIdx.x] = 0;
    __syncthreads();
    int n = blockIdx.x * blockDim.x + threadIdx.x;
    int t = 0, loc = 0;
    bool v = (n < NN);
    if (v) { t = nt[n]; loc = atomicAdd(&h[t], 1); }
    __syncthreads();
    if (threadIdx.x < TT && h[threadIdx.x])
        base[threadIdx.x] = atomicAdd(&g_cur[threadIdx.x], h[threadIdx.x]);
    __syncthreads();
    if (v) g_list[base[t] + loc] = n;
}

// ---------------- presplit: fp32 -> half hi/lo --------------------------------
__global__ void k_splitf(const float* __restrict__ src, __half* __restrict__ dh,
                         __half* __restrict__ dl, int n) {
    int i = blockIdx.x * blockDim.x + threadIdx.x;
    if (i >= n) return;
    float x = src[i];
    __half h, l; splith(x, h, l);
    dh[i] = h; dl[i] = l;
}

// ---------------- exact fp32 weight combine: C(+y*cs) = A(+y*as) @ B(+y*bs) --
__global__ void wcomb(const float* __restrict__ A, long long as,
                      const float* __restrict__ Bm, long long bs,
                      float* __restrict__ C, long long cs) {
    int y = blockIdx.y;
    A += (long long)y * as; Bm += (long long)y * bs; C += (long long)y * cs;
    int bm = blockIdx.x * 64;
    __shared__ float Xs[64][8];
    __shared__ float Ws[8][128];
    int tid = threadIdx.x, ty = tid >> 5, tx = tid & 31;
    float acc[8][4];
    #pragma unroll
    for (int i = 0; i < 8; i++)
        #pragma unroll
        for (int j = 0; j < 4; j++) acc[i][j] = 0.f;
    for (int kb = 0; kb < 16; kb++) {
        {
            int m = tid >> 2, kq = (tid & 3) << 1;
            float2 xv = *(const float2*)(A + (long long)(bm + m) * DD + kb * 8 + kq);
            Xs[m][kq] = xv.x; Xs[m][kq + 1] = xv.y;
            int kk = tid >> 5, c4 = (tid & 31) << 2;
            *(float4*)&Ws[kk][c4] = *(const float4*)(Bm + (long long)(kb * 8 + kk) * DD + c4);
        }
        __syncthreads();
        #pragma unroll
        for (int kk = 0; kk < 8; kk++) {
            float4 b = *(float4*)&Ws[kk][tx << 2];
            #pragma unroll
            for (int i = 0; i < 8; i++) {
                float a = Xs[ty * 8 + i][kk];
                acc[i][0] += a * b.x; acc[i][1] += a * b.y;
                acc[i][2] += a * b.z; acc[i][3] += a * b.w;
            }
        }
        __syncthreads();
    }
    #pragma unroll
    for (int i = 0; i < 8; i++) {
        float4 o;
        o.x = acc[i][0]; o.y = acc[i][1]; o.z = acc[i][2]; o.w = acc[i][3];
        *(float4*)(C + (long long)(bm + ty * 8 + i) * DD + (tx << 2)) = o;
    }
}

// ---------------- bf[k] = bq @ Wak[k] -----------------------------------------
__global__ void k_bf(const float* __restrict__ bq, const float* __restrict__ Wak) {
    int k = blockIdx.x, n = threadIdx.x;
    float s = 0.f;
    for (int d = 0; d < DD; d++) s += bq[d] * Wak[((long long)k * DD + d) * DD + n];
    g_bf[k * DD + n] = s;
}

// ------ presplit-input fp16 tensor GEMM: C[rows] = X[rows] @ W + B -----------
// 128x128 tile, K=128 in 2 stages of 64. 8 warps (4M x 2N), cp.async staging.
// acc += Ahi*Whi + Alo*Whi + Ahi*Wlo  (fp32 accumulate).
__global__ __launch_bounds__(256, 2) void tc_gemm2(
    const __half* __restrict__ Xh, const __half* __restrict__ Xl, long long xs,
    const __half* __restrict__ Wh, const __half* __restrict__ Wl,
    const float* __restrict__ B, long long bs,
    float* __restrict__ C, long long cs,
    int typed, int nrows)
{
    extern __shared__ char smc[];
    float* biasp = (float*)(smc + O2_BIAS);
    uint32_t sb = smem_u32(smc);

    int gy = blockIdx.y;
    const int* rows = nullptr;
    int cnt;
    if (typed) {
        rows = g_list + g_off[gy];
        cnt = g_cnt[gy];
    } else {
        Xh += (long long)gy * xs;
        Xl += (long long)gy * xs;
        C += (long long)gy * cs;
        cnt = nrows;
    }
    Wh += (long long)gy * (DD * DD);
    Wl += (long long)gy * (DD * DD);
    if (B) B += (long long)gy * bs;
    int bm = blockIdx.x * 128;
    if (bm >= cnt) return;

    int tid = threadIdx.x, wid = tid >> 5, lane = tid & 31;
    if (tid < 128) biasp[tid] = B ? B[tid] : 0.f;

    int warpM = wid & 3, warpN = wid >> 2;
    int rbase = warpM * 32, cbase = warpN * 64;
    int qid = lane >> 2, tq = lane & 3;

    int li = lane & 7, ls = lane >> 3;
    int a_row = li + ((ls & 1) << 3);
    int a_col = ((ls >> 1) & 1) << 3;
    int b_krow = li + ((ls >> 1) << 3);
    int b_ncol = (ls & 1) << 3;

    uint32_t aoff = sb + (uint32_t)(rbase + a_row) * 176u + (uint32_t)a_col * 2u;
    uint32_t boff = sb + O2_BH + (uint32_t)b_krow * 272u + (uint32_t)(cbase + b_ncol) * 2u;

    float acc[2][8][4];
    #pragma unroll
    for (int mi = 0; mi < 2; mi++)
        #pragma unroll
        for (int ni = 0; ni < 8; ni++)
            #pragma unroll
            for (int j = 0; j < 4; j++) acc[mi][ni][j] = 0.f;

    for (int st = 0; st < 2; st++) {
        if (st) __syncthreads();
        // A: 128 rows x 64 halves x 2 planes = 2048 16B-chunks
        #pragma unroll
        for (int it = 0; it < 8; it++) {
            int s = tid + it * 256;
            int r = s >> 4, cc = s & 15;
            int plane = cc >> 3, c16 = cc & 7;
            int gr = bm + r;
            int row = (gr < cnt) ? (rows ? rows[gr] : gr) : 0;
            unsigned sz = (gr < cnt) ? 16u : 0u;
            const __half* srcp = (plane ? Xl : Xh) + (long long)row * DD + st * 64 + c16 * 8;
            uint32_t dst = sb + (plane ? O2_AL : O2_AH) + (uint32_t)r * 176u + (uint32_t)c16 * 16u;
            CPA16(dst, srcp, sz);
        }
        // B: 64 k-rows x 128 halves x 2 planes = 2048 chunks
        #pragma unroll
        for (int it = 0; it < 8; it++) {
            int s = tid + it * 256;
            int k = s >> 5, cc = s & 31;
            int plane = cc >> 4, c16 = cc & 15;
            const __half* srcp = (plane ? Wl : Wh) + (long long)(st * 64 + k) * DD + c16 * 8;
            uint32_t dst = sb + (plane ? O2_BL : O2_BH) + (uint32_t)k * 272u + (uint32_t)c16 * 16u;
            CPA16(dst, srcp, 16u);
        }
        CPA_WAIT();
        __syncthreads();

        #pragma unroll
        for (int ks = 0; ks < 4; ks++) {
            uint32_t ka = aoff + (uint32_t)ks * 32u;
            uint32_t ah[2][4], al[2][4];
            LDSM4(ah[0], ka);
            LDSM4(ah[1], ka + 16u * 176u);
            LDSM4(al[0], ka + (uint32_t)O2_AL);
            LDSM4(al[1], ka + (uint32_t)O2_AL + 16u * 176u);
            #pragma unroll
            for (int nf = 0; nf < 4; nf++) {
                uint32_t kb = boff + (uint32_t)ks * 4352u + (uint32_t)nf * 32u;
                uint32_t bhf[4], blf[4];
                LDSM4T(bhf, kb);
                LDSM4T(blf, kb + (uint32_t)(O2_BL - O2_BH));
                #pragma unroll
                for (int j = 0; j < 2; j++) {
                    #pragma unroll
                    for (int mi = 0; mi < 2; mi++) {
                        float* a4 = acc[mi][nf * 2 + j];
                        MMA16(a4, ah[mi], bhf[j], bhf[2 + j]);
                        MMA16(a4, al[mi], bhf[j], bhf[2 + j]);
                        MMA16(a4, ah[mi], blf[j], blf[2 + j]);
                    }
                }
            }
        }
    }

    #pragma unroll
    for (int ni = 0; ni < 8; ni++) {
        int col = cbase + ni * 8 + tq * 2;
        float bx = biasp[col], by = biasp[col + 1];
        #pragma unroll
        for (int mi = 0; mi < 2; mi++) {
            int r0 = bm + rbase + mi * 16 + qid;
            if (r0 < cnt) {
                int row = rows ? rows[r0] : r0;
                float2 o = make_float2(acc[mi][ni][0] + bx, acc[mi][ni][1] + by);
                *(float2*)(C + (long long)row * DD + col) = o;
            }
            int r1 = r0 + 8;
            if (r1 < cnt) {
                int row = rows ? rows[r1] : r1;
                float2 o = make_float2(acc[mi][ni][2] + bx, acc[mi][ni][3] + by);
                *(float2*)(C + (long long)row * DD + col) = o;
            }
        }
    }
}

// ---------------- qA = rel_att-transformed q ----------------------------------
__global__ void k_qA(const float* __restrict__ rel_att) {
    extern __shared__ float Ashm[];
    for (int i = threadIdx.x; i < RR * HH * DKK * DKK; i += blockDim.x) {
        int rh = i >> 10, dm = i & 1023, d = dm >> 5, m = dm & 31;
        Ashm[(rh * 32 + m) * 32 + d] = rel_att[i];
    }
    __syncthreads();
    int lane = threadIdx.x & 31;
    int gw = (blockIdx.x * blockDim.x + threadIdx.x) >> 5;
    int nw = (gridDim.x * blockDim.x) >> 5;
    for (int n = gw; n < NN; n += nw) {
        float qr[HH];
        #pragma unroll
        for (int h = 0; h < HH; h++) qr[h] = g_q[n * DD + h * 32 + lane];
        #pragma unroll
        for (int h = 0; h < HH; h++) {
            float a0 = 0, a1 = 0, a2 = 0, a3 = 0, a4 = 0;
            #pragma unroll
            for (int m = 0; m < 32; m++) {
                float qm = __shfl_sync(0xffffffffu, qr[h], m);
                int base = (h * 32 + m) * 32 + lane;
                a0 += Ashm[base        ] * qm;
                a1 += Ashm[base +  4096] * qm;
                a2 += Ashm[base +  8192] * qm;
                a3 += Ashm[base + 12288] * qm;
                a4 += Ashm[base + 16384] * qm;
            }
            g_qA[((n * RR + 0) * HH + h) * 32 + lane] = a0;
            g_qA[((n * RR + 1) * HH + h) * 32 + lane] = a1;
            g_qA[((n * RR + 2) * HH + h) * 32 + lane] = a2;
            g_qA[((n * RR + 3) * HH + h) * 32 + lane] = a3;
            g_qA[((n * RR + 4) * HH + h) * 32 + lane] = a4;
        }
    }
}

// ---------------- edge logits + segment max + degree ----------------
__global__ void k_logits(const int* __restrict__ ei, const int* __restrict__ et,
                         const float* __restrict__ rel_pri) {
    int lane = threadIdx.x & 31;
    int gw = (blockIdx.x * blockDim.x + threadIdx.x) >> 5;
    int nw = (gridDim.x * blockDim.x) >> 5;
    for (int e = gw; e < EE; e += nw) {
        int s = ei[e], tg = ei[EE + e], r = et[e];
        float p0, p1, p2, p3;
        {
            const float* kb = g_k + (long long)s * DD;
            const float* qa = g_qA + ((long long)tg * RR + r) * DD;
            p0 = kb[lane]      * qa[lane];
            p1 = kb[32 + lane] * qa[32 + lane];
            p2 = kb[64 + lane] * qa[64 + lane];
            p3 = kb[96 + lane] * qa[96 + lane];
        }
        p0 = warp_sum(p0); p1 = warp_sum(p1); p2 = warp_sum(p2); p3 = warp_sum(p3);
        if (lane == 0) {
            atomicAdd(&g_deg[tg], 1);
            float l0 = p0 * rel_pri[r * HH + 0] * INV_SQRT_DK;
            float l1 = p1 * rel_pri[r * HH + 1] * INV_SQRT_DK;
            float l2 = p2 * rel_pri[r * HH + 2] * INV_SQRT_DK;
            float l3 = p3 * rel_pri[r * HH + 3] * INV_SQRT_DK;
            g_logits[e * HH + 0] = l0; g_logits[e * HH + 1] = l1;
            g_logits[e * HH + 2] = l2; g_logits[e * HH + 3] = l3;
            atomicMax(&g_mx[tg * HH + 0], enc_f(l0));
            atomicMax(&g_mx[tg * HH + 1], enc_f(l1));
            atomicMax(&g_mx[tg * HH + 2], enc_f(l2));
            atomicMax(&g_mx[tg * HH + 3], enc_f(l3));
        }
    }
}

// ---------------- exp + segment sum ----------------
__global__ void k_exp(const int* __restrict__ ei) {
    int idx = blockIdx.x * blockDim.x + threadIdx.x;
    if (idx >= EE * HH) return;
    int e = idx >> 2, h = idx & 3;
    int tg = ei[EE + e];
    float ex = expf(g_logits[idx] - dec_f(g_mx[tg * HH + h]));
    g_logits[idx] = ex;
    atomicAdd(&g_sum[tg * HH + h], ex);
}

// ------- messages / agg (edge n < N shortcut); writes SPLIT halves -----------
__global__ void k_msg(const float* __restrict__ rel_msg, const int* __restrict__ ei,
                      const int* __restrict__ et) {
    extern __shared__ float Ms[];
    for (int i = threadIdx.x; i < RR * HH * DKK * DKK; i += blockDim.x) Ms[i] = rel_msg[i];
    __syncthreads();
    int lane = threadIdx.x & 31;
    int gw = (blockIdx.x * blockDim.x + threadIdx.x) >> 5;
    int nw = (gridDim.x * blockDim.x) >> 5;
    for (int n = gw; n < NN; n += nw) {
        int s = ei[n], tg = ei[EE + n], r = et[n];
        float deg = (float)g_deg[n];
        float vr[HH];
        #pragma unroll
        for (int h = 0; h < HH; h++) vr[h] = g_v[(long long)s * DD + h * 32 + lane];
        #pragma unroll
        for (int h = 0; h < HH; h++) {
            float att = g_logits[n * HH + h] / (g_sum[tg * HH + h] + 1e-16f);
            float vp = 0.f;
            const float* Mb = Ms + (r * HH + h) * 1024;
            #pragma unroll
            for (int d = 0; d < 32; d++) {
                float vd = __shfl_sync(0xffffffffu, vr[h], d);
                vp += Mb[d * 32 + lane] * vd;
            }
            float base = deg * att;
            int o = n * DD + h * 32 + lane;
            float vp2 = vp * vp;
            float m1 = base * vp;
            float m2 = base * vp2;
            float m3 = signed_cbrt(base * vp2 * vp);
            __half hh, ll;
            splith(m1, hh, ll); g_aggh[o] = hh;          g_aggl[o] = ll;
            splith(m2, hh, ll); g_aggh[ND + o] = hh;     g_aggl[ND + o] = ll;
            splith(m3, hh, ll); g_aggh[2 * ND + o] = hh; g_aggl[2 * ND + o] = ll;
        }
    }
}

// -- gating: res = sum_k sigmoid(front.tail)*aggm; writes split(gelu(res)) ----
__global__ void k_gate() {
    int w = (blockIdx.x * blockDim.x + threadIdx.x) >> 5;
    int lane = threadIdx.x & 31;
    if (w >= NN) return;
    int o = w * DD + lane * 4;
    float4 r4 = make_float4(0.f, 0.f, 0.f, 0.f);
    #pragma unroll
    for (int k = 0; k < KKM; k++) {
        float4 f = *(float4*)&g_front[k * ND + o];
        float4 t = *(float4*)&g_tail[k * ND + o];
        float p = f.x * t.x + f.y * t.y + f.z * t.z + f.w * t.w;
        p = warp_sum(p);
        float gate = 1.f / (1.f + expf(-p));
        float4 a = *(float4*)&g_aggm[k * ND + o];
        r4.x += gate * a.x; r4.y += gate * a.y; r4.z += gate * a.z; r4.w += gate * a.w;
    }
    float y0 = gelu_exact(r4.x), y1 = gelu_exact(r4.y);
    float y2 = gelu_exact(r4.z), y3 = gelu_exact(r4.w);
    __half h0, h1, h2, h3, l0, l1, l2, l3;
    splith(y0, h0, l0); splith(y1, h1, l1);
    splith(y2, h2, l2); splith(y3, h3, l3);
    *(__half2*)&g_resh[o]     = __halves2half2(h0, h1);
    *(__half2*)&g_resh[o + 2] = __halves2half2(h2, h3);
    *(__half2*)&g_resl[o]     = __halves2half2(l0, l1);
    *(__half2*)&g_resl[o + 2] = __halves2half2(l2, l3);
}

// ---------------- skip blend + LayerNorm --------------------------------------
__global__ void k_postln(const int* __restrict__ nt, const float* __restrict__ xin,
                         const float* __restrict__ skip, const float* __restrict__ lng,
                         const float* __restrict__ lnb, float* __restrict__ out) {
    int wid = (blockIdx.x * blockDim.x + threadIdx.x) >> 5;
    int lane = threadIdx.x & 31;
    if (wid >= NN) return;
    int t = nt[wid];
    float alpha = 1.f / (1.f + expf(-skip[t]));
    int o = wid * DD + lane * 4;
    float4 tr = *(float4*)&g_trans[o];
    float4 xv = *(const float4*)(xin + o);
    float y0 = tr.x * alpha + xv.x * (1.f - alpha);
    float y1 = tr.y * alpha + xv.y * (1.f - alpha);
    float y2 = tr.z * alpha + xv.z * (1.f - alpha);
    float y3 = tr.w * alpha + xv.w * (1.f - alpha);
    float s  = y0 + y1 + y2 + y3;
    float ss = y0 * y0 + y1 * y1 + y2 * y2 + y3 * y3;
    #pragma unroll
    for (int of = 16; of > 0; of >>= 1) {
        s  += __shfl_xor_sync(0xffffffffu, s,  of);
        ss += __shfl_xor_sync(0xffffffffu, ss, of);
    }
    float mu  = s * (1.f / 128.f);
    float inv = rsqrtf(ss * (1.f / 128.f) - mu * mu + 1e-5f);
    float4 gg = *(const float4*)(lng + t * DD + lane * 4);
    float4 bb = *(const float4*)(lnb + t * DD + lane * 4);
    float4 o4;
    o4.x = (y0 - mu) * inv * gg.x + bb.x;
    o4.y = (y1 - mu) * inv * gg.y + bb.y;
    o4.z = (y2 - mu) * inv * gg.z + bb.z;
    o4.w = (y3 - mu) * inv * gg.w + bb.w;
    *(float4*)(out + (long long)wid * DD + lane * 4) = o4;
}

// ---------------- launch ----------------
extern "C" void kernel_launch(void* const* d_in, const int* in_sizes, int n_in,
                              void* d_out, int out_size) {
    const float* meta_xs  = (const float*)d_in[0];
    const int*   node_type= (const int*)  d_in[1];
    const int*   edge_idx = (const int*)  d_in[2];
    const int*   edge_type= (const int*)  d_in[3];
    const float* q_w = (const float*)d_in[5],  *q_b = (const float*)d_in[6];
    const float* k_w = (const float*)d_in[7],  *k_b = (const float*)d_in[8];
    const float* v_w = (const float*)d_in[9],  *v_b = (const float*)d_in[10];
    const float* a_w = (const float*)d_in[11], *a_b = (const float*)d_in[12];
    const float* rel_pri = (const float*)d_in[13];
    const float* rel_att = (const float*)d_in[14];
    const float* rel_msg = (const float*)d_in[15];
    const float* WMk = (const float*)d_in[16];
    const float* Wak = (const float*)d_in[17];
    const float* Wq  = (const float*)d_in[18], *bq  = (const float*)d_in[19];
    const float* Wkl = (const float*)d_in[20], *bkl = (const float*)d_in[21];
    const float* skip= (const float*)d_in[22];
    const float* lng = (const float*)d_in[23], *lnb = (const float*)d_in[24];
    float* out = (float*)d_out;

    cudaFuncSetAttribute(k_qA,     cudaFuncAttributeMaxDynamicSharedMemorySize, 81920);
    cudaFuncSetAttribute(k_msg,    cudaFuncAttributeMaxDynamicSharedMemorySize, 81920);
    cudaFuncSetAttribute(tc_gemm2, cudaFuncAttributeMaxDynamicSharedMemorySize, GSM2);

    void *pq, *pk, *pv, *paggm, *pfront, *ptail, *ptrans, *pWt, *pWf, *pbf;
    void *pxh, *pxl, *paggh, *paggl, *presh, *presl, *pwh, *pwl;
    cudaGetSymbolAddress(&pq, g_q);
    cudaGetSymbolAddress(&pk, g_k);
    cudaGetSymbolAddress(&pv, g_v);
    cudaGetSymbolAddress(&paggm, g_aggm);
    cudaGetSymbolAddress(&pfront, g_front);
    cudaGetSymbolAddress(&ptail, g_tail);
    cudaGetSymbolAddress(&ptrans, g_trans);
    cudaGetSymbolAddress(&pWt, g_Wt);
    cudaGetSymbolAddress(&pWf, g_Wf);
    cudaGetSymbolAddress(&pbf, g_bf);
    cudaGetSymbolAddress(&pxh, g_xh);
    cudaGetSymbolAddress(&pxl, g_xl);
    cudaGetSymbolAddress(&paggh, g_aggh);
    cudaGetSymbolAddress(&paggl, g_aggl);
    cudaGetSymbolAddress(&presh, g_resh);
    cudaGetSymbolAddress(&presl, g_resl);
    cudaGetSymbolAddress(&pwh, g_wh);
    cudaGetSymbolAddress(&pwl, g_wl);

    const int MSZ = DD * DD;                    // 16384
    __half* wh = (__half*)pwh; __half* wl = (__half*)pwl;

    k_init<<<512, 256>>>();
    k_count<<<(NN + 255) / 256, 256>>>(node_type);
    k_offs<<<1, 1>>>();
    k_scatter<<<(NN + 255) / 256, 256>>>(node_type);

    // exact fp32 weight combines
    wcomb<<<dim3(2, KKM), 256>>>(WMk, MSZ, Wkl, 0, (float*)pWt, MSZ);
    wcomb<<<dim3(2, KKM), 256>>>(Wq, 0, Wak, MSZ, (float*)pWf, MSZ);
    k_bf<<<KKM, 128>>>(bq, Wak);

    // presplits: X + 21 weight matrices
    // slots: qw 0-2, kw 3-5, vw 6-8, aw 9-11, WMk 12-14, Wt 15-17, Wf 18-20
    k_splitf<<<(ND + 255) / 256, 256>>>(meta_xs, (__half*)pxh, (__half*)pxl, ND);
    k_splitf<<<(3 * MSZ + 255) / 256, 256>>>(q_w, wh + 0 * MSZ,  wl + 0 * MSZ,  3 * MSZ);
    k_splitf<<<(3 * MSZ + 255) / 256, 256>>>(k_w, wh + 3 * MSZ,  wl + 3 * MSZ,  3 * MSZ);
    k_splitf<<<(3 * MSZ + 255) / 256, 256>>>(v_w, wh + 6 * MSZ,  wl + 6 * MSZ,  3 * MSZ);
    k_splitf<<<(3 * MSZ + 255) / 256, 256>>>(a_w, wh + 9 * MSZ,  wl + 9 * MSZ,  3 * MSZ);
    k_splitf<<<(3 * MSZ + 255) / 256, 256>>>(WMk, wh + 12 * MSZ, wl + 12 * MSZ, 3 * MSZ);
    k_splitf<<<(3 * MSZ + 255) / 256, 256>>>((float*)pWt, wh + 15 * MSZ, wl + 15 * MSZ, 3 * MSZ);
    k_splitf<<<(3 * MSZ + 255) / 256, 256>>>((float*)pWf, wh + 18 * MSZ, wl + 18 * MSZ, 3 * MSZ);

    dim3 gT((NN + 127) / 128, TT);
    dim3 gK((NN + 127) / 128, KKM);
    __half* xh = (__half*)pxh; __half* xl = (__half*)pxl;
    __half* aggh = (__half*)paggh; __half* aggl = (__half*)paggl;

    // typed projections q,k,v
    tc_gemm2<<<gT, 256, GSM2>>>(xh, xl, 0, wh + 0 * MSZ, wl + 0 * MSZ,
                                q_b, DD, (float*)pq, 0, 1, 0);
    tc_gemm2<<<gT, 256, GSM2>>>(xh, xl, 0, wh + 3 * MSZ, wl + 3 * MSZ,
                                k_b, DD, (float*)pk, 0, 1, 0);
    tc_gemm2<<<gT, 256, GSM2>>>(xh, xl, 0, wh + 6 * MSZ, wl + 6 * MSZ,
                                v_b, DD, (float*)pv, 0, 1, 0);

    // qA, edge logits, softmax, messages (writes split agg)
    k_qA<<<592, 256, 81920>>>(rel_att);
    k_logits<<<2368, 256>>>(edge_idx, edge_type, rel_pri);
    k_exp<<<(EE * HH + 255) / 256, 256>>>(edge_idx);
    k_msg<<<592, 256, 81920>>>(rel_msg, edge_idx, edge_type);

    // aggm[k] = aggX[k] @ WMk[k]
    tc_gemm2<<<gK, 256, GSM2>>>(aggh, aggl, ND, wh + 12 * MSZ, wl + 12 * MSZ,
                                nullptr, 0, (float*)paggm, ND, 0, NN);
    // tail[k] = aggX[k] @ Wt[k] + bkl
    tc_gemm2<<<gK, 256, GSM2>>>(aggh, aggl, ND, wh + 15 * MSZ, wl + 15 * MSZ,
                                bkl, 0, (float*)ptail, ND, 0, NN);
    // front[k] = x @ Wf[k] + bf[k]
    tc_gemm2<<<gK, 256, GSM2>>>(xh, xl, 0, wh + 18 * MSZ, wl + 18 * MSZ,
                                (const float*)pbf, DD, (float*)pfront, ND, 0, NN);

    // gating -> split(gelu(res))
    k_gate<<<(NN * 32 + 255) / 256, 256>>>();

    // trans = typed a_w GEMM over gelu(res)
    tc_gemm2<<<gT, 256, GSM2>>>((__half*)presh, (__half*)presl, 0,
                                wh + 9 * MSZ, wl + 9 * MSZ,
                                a_b, DD, (float*)ptrans, 0, 1, 0);
    // skip blend + LayerNorm
    k_postln<<<(NN * 32 + 255) / 256, 256>>>(node_type, meta_xs, skip, lng, lnb, out);
}

// round 9
// speedup vs baseline: 2.1240x; 1.0181x over previous
#include <cuda_runtime.h>
#include <cuda_fp16.h>
#include <math.h>
#include <stdint.h>

#define NN 40000
#define EE 320000
#define DD 128
#define HH 4
#define TT 3
#define RR 5
#define KKM 3
#define DKK 32
#define ND (NN*DD)
#define MSZ (DD*DD)
#define NPART 157
#define INV_SQRT_DK 0.17677669529663687f   // 1/sqrt(32)

// tc_gemm_ms smem layout (bytes): A full-K 128 rows x 272B x 2 planes,
// B one 64-k stage x 272B x 2 planes.
#define M_AH 0
#define M_AL 34816
#define M_BH 69632
#define M_BL 87040
#define GSM_MS 104448

// ---------------- scratch (device globals; no allocation allowed) -------------
__device__ float    g_q[ND];
__device__ float    g_k[ND];
__device__ float    g_v[ND];
__device__ float    g_qA[NN*RR*DD];
__device__ float    g_logits[EE*HH];
__device__ unsigned g_mx[NN*HH];
__device__ float    g_sum[NN*HH];
__device__ int      g_deg[NN];
__device__ float    g_aggm[KKM*ND];
__device__ float    g_front[KKM*ND];
__device__ float    g_tail[KKM*ND];
__device__ float    g_trans[ND];
__device__ float    g_Wt[KKM*MSZ];       // WMk[k] @ Wkl (fp32 exact)
__device__ float    g_Wf[KKM*MSZ];       // Wq @ Wak[k]  (fp32 exact)
__device__ float    g_bf[KKM*DD];        // bq @ Wak[k]
// presplit half planes
__device__ __half   g_xh[ND],        g_xl[ND];          // split(meta_xs)
__device__ __half   g_aggh[KKM*ND],  g_aggl[KKM*ND];    // split(xform(agg))
__device__ __half   g_resh[ND],      g_resl[ND];        // split(gelu(res))
__device__ __half   g_wh[21*MSZ],    g_wl[21*MSZ];      // 21 weight matrices
__device__ int      g_list[NN];
__device__ int      g_part[NPART*TT];
__device__ int      g_cnt[TT];
__device__ int      g_off[TT];
__device__ int      g_cur[TT];

// ---------------- helpers ----------------
__device__ __forceinline__ unsigned enc_f(float f) {
    unsigned u = __float_as_uint(f);
    return (u & 0x80000000u) ? ~u : (u | 0x80000000u);
}
__device__ __forceinline__ float dec_f(unsigned u) {
    return (u & 0x80000000u) ? __uint_as_float(u & 0x7fffffffu) : __uint_as_float(~u);
}
__device__ __forceinline__ float signed_cbrt(float a) {
    float s = (a > 0.f) ? 1.f : ((a < 0.f) ? -1.f : 0.f);
    return s * cbrtf(fabsf(a) + 1e-18f);
}
__device__ __forceinline__ float gelu_exact(float x) {
    return 0.5f * x * (1.f + erff(x * 0.70710678118654752440f));
}
__device__ __forceinline__ float warp_sum(float p) {
    #pragma unroll
    for (int o = 16; o > 0; o >>= 1) p += __shfl_xor_sync(0xffffffffu, p, o);
    return p;
}
__device__ __forceinline__ void splith(float x, __half& hi, __half& lo) {
    __half h = __float2half_rn(x);
    hi = h;
    lo = __float2half_rn(x - __half2float(h));
}
__device__ __forceinline__ uint32_t smem_u32(const void* p) {
    uint32_t a;
    asm("{ .reg .u64 t; cvta.to.shared.u64 t, %1; cvt.u32.u64 %0, t; }" : "=r"(a) : "l"(p));
    return a;
}

#define CPA16(dst, src, sz)                                                   \
    asm volatile("cp.async.ca.shared.global [%0], [%1], 16, %2;"              \
        :: "r"(dst), "l"(src), "r"(sz))
#define CPA_WAIT()                                                            \
    do { asm volatile("cp.async.commit_group;" ::: "memory");                 \
         asm volatile("cp.async.wait_group 0;" ::: "memory"); } while (0)
#define LDSM4(r, addr)                                                        \
    asm volatile("ldmatrix.sync.aligned.m8n8.x4.shared.b16 {%0,%1,%2,%3}, [%4];" \
        : "=r"((r)[0]), "=r"((r)[1]), "=r"((r)[2]), "=r"((r)[3]) : "r"(addr))
#define LDSM4T(r, addr)                                                       \
    asm volatile("ldmatrix.sync.aligned.m8n8.x4.trans.shared.b16 {%0,%1,%2,%3}, [%4];" \
        : "=r"((r)[0]), "=r"((r)[1]), "=r"((r)[2]), "=r"((r)[3]) : "r"(addr))
#define MMA16(acc, a, b0, b1)                                                 \
    asm volatile("mma.sync.aligned.m16n8k16.row.col.f32.f16.f16.f32 "         \
        "{%0,%1,%2,%3}, {%4,%5,%6,%7}, {%8,%9}, {%0,%1,%2,%3};"               \
        : "+f"((acc)[0]), "+f"((acc)[1]), "+f"((acc)[2]), "+f"((acc)[3])      \
        : "r"((a)[0]), "r"((a)[1]), "r"((a)[2]), "r"((a)[3]), "r"(b0), "r"(b1))

// ---------------- bucketing (no pre-zero needed: partials overwritten) --------
__global__ void k_count(const int* __restrict__ nt) {
    __shared__ int h[TT];
    int tid = threadIdx.x;
    if (tid < TT) h[tid] = 0;
    __syncthreads();
    int n = blockIdx.x * blockDim.x + tid;
    if (n < NN) atomicAdd(&h[nt[n]], 1);
    __syncthreads();
    if (tid < TT) g_part[blockIdx.x * TT + tid] = h[tid];
}
__global__ void k_offs() {
    __shared__ int cs[TT];
    int w = threadIdx.x >> 5, lane = threadIdx.x & 31;
    if (w < TT) {
        int s = 0;
        for (int i = lane; i < NPART; i += 32) s += g_part[i * TT + w];
        #pragma unroll
        for (int o = 16; o > 0; o >>= 1) s += __shfl_xor_sync(0xffffffffu, s, o);
        if (lane == 0) { g_cnt[w] = s; cs[w] = s; }
    }
    __syncthreads();
    if (threadIdx.x == 0) {
        int o = 0;
        for (int t = 0; t < TT; t++) { g_off[t] = o; g_cur[t] = o; o += cs[t]; }
    }
}
__global__ void k_scatter(const int* __restrict__ nt) {
    __shared__ int h[TT], base[TT];
    if (threadIdx.x < TT) h[threadIdx.x] = 0;
    __syncthreads();
    int n = blockIdx.x * blockDim.x + threadIdx.x;
    int t = 0, loc = 0;
    bool v = (n < NN);
    if (v) { t = nt[n]; loc = atomicAdd(&h[t], 1); }
    __syncthreads();
    if (threadIdx.x < TT && h[threadIdx.x])
        base[threadIdx.x] = atomicAdd(&g_cur[threadIdx.x], h[threadIdx.x]);
    __syncthreads();
    if (v) g_list[base[t] + loc] = n;
}

// ------ combined exact fp32 weight combines + bf --------------------------
// y<3: Wt[y]=WMk[y]@Wkl ; y in 3..5: Wf[y-3]=Wq@Wak[y-3] ; y==6: bf
__global__ void wcomb_all(const float* __restrict__ WMk, const float* __restrict__ Wkl,
                          const float* __restrict__ Wq, const float* __restrict__ Wak,
                          const float* __restrict__ bq) {
    int y = blockIdx.y;
    if (y == 6) {
        if (blockIdx.x) return;
        for (int idx = threadIdx.x; idx < KKM * DD; idx += blockDim.x) {
            int k = idx >> 7, n = idx & 127;
            float s = 0.f;
            for (int d = 0; d < DD; d++) s += bq[d] * Wak[((long long)k * DD + d) * DD + n];
            g_bf[idx] = s;
        }
        return;
    }
    const float* A; const float* Bm; float* C;
    if (y < 3) { A = WMk + (long long)y * MSZ; Bm = Wkl;               C = g_Wt + (long long)y * MSZ; }
    else       { A = Wq;                        Bm = Wak + (long long)(y-3) * MSZ; C = g_Wf + (long long)(y-3) * MSZ; }
    int bm = blockIdx.x * 64;
    __shared__ float Xs[64][8];
    __shared__ float Ws[8][128];
    int tid = threadIdx.x, ty = tid >> 5, tx = tid & 31;
    float acc[8][4];
    #pragma unroll
    for (int i = 0; i < 8; i++)
        #pragma unroll
        for (int j = 0; j < 4; j++) acc[i][j] = 0.f;
    for (int kb = 0; kb < 16; kb++) {
        {
            int m = tid >> 2, kq = (tid & 3) << 1;
            float2 xv = *(const float2*)(A + (long long)(bm + m) * DD + kb * 8 + kq);
            Xs[m][kq] = xv.x; Xs[m][kq + 1] = xv.y;
            int kk = tid >> 5, c4 = (tid & 31) << 2;
            *(float4*)&Ws[kk][c4] = *(const float4*)(Bm + (long long)(kb * 8 + kk) * DD + c4);
        }
        __syncthreads();
        #pragma unroll
        for (int kk = 0; kk < 8; kk++) {
            float4 b = *(float4*)&Ws[kk][tx << 2];
            #pragma unroll
            for (int i = 0; i < 8; i++) {
                float a = Xs[ty * 8 + i][kk];
                acc[i][0] += a * b.x; acc[i][1] += a * b.y;
                acc[i][2] += a * b.z; acc[i][3] += a * b.w;
            }
        }
        __syncthreads();
    }
    #pragma unroll
    for (int i = 0; i < 8; i++) {
        float4 o;
        o.x = acc[i][0]; o.y = acc[i][1]; o.z = acc[i][2]; o.w = acc[i][3];
        *(float4*)(C + (long long)(bm + ty * 8 + i) * DD + (tx << 2)) = o;
    }
}

// ---------------- presplit everything in one pass -----------------------------
// layout of g_wh/g_wl slots: 0-2 qw, 3-5 kw, 6-8 vw, 9-11 aw, 12-14 WMk,
// 15-17 Wt, 18-20 Wf
__global__ void k_splitall(const float* __restrict__ x,
                           const float* __restrict__ qw, const float* __restrict__ kw,
                           const float* __restrict__ vw, const float* __restrict__ aw,
                           const float* __restrict__ WMk) {
    long long total = (long long)ND + 21LL * MSZ;
    long long i = (long long)blockIdx.x * blockDim.x + threadIdx.x;
    if (i >= total) return;
    float s;
    __half h, l;
    if (i < ND) {
        s = x[i];
        splith(s, h, l);
        g_xh[i] = h; g_xl[i] = l;
    } else {
        long long wi = i - ND;
        if      (wi <  3LL * MSZ) s = qw[wi];
        else if (wi <  6LL * MSZ) s = kw[wi - 3LL * MSZ];
        else if (wi <  9LL * MSZ) s = vw[wi - 6LL * MSZ];
        else if (wi < 12LL * MSZ) s = aw[wi - 9LL * MSZ];
        else if (wi < 15LL * MSZ) s = WMk[wi - 12LL * MSZ];
        else if (wi < 18LL * MSZ) s = g_Wt[wi - 15LL * MSZ];
        else                      s = g_Wf[wi - 18LL * MSZ];
        splith(s, h, l);
        g_wh[wi] = h; g_wl[wi] = l;
    }
}

// ------ multi-set fp16-split tensor GEMM ------------------------------------
// One block: 128x128 tile. Stages full-K A ONCE (272B pitch, hi/lo planes),
// then loops over up to 6 weight sets, staging B per 64-k stage.
// acc += Ahi*Whi + Alo*Whi + Ahi*Wlo  (fp32 accumulate).
struct GMSet {
    int wslot;          // slot into g_wh/g_wl
    int waddgy;         // add blockIdx.y to slot?
    const float* bias;  // may be null
    int baddgy;         // bias += gy*DD ?
    float* out;
    long long ogys;     // out += gy*ogys
};
struct GMArgs { GMSet s[6]; int n; };

__global__ __launch_bounds__(256, 2) void tc_gemm_ms(
    const __half* __restrict__ Xh, const __half* __restrict__ Xl, long long xgys,
    int typed, int nrows, GMArgs args)
{
    extern __shared__ char smc[];
    uint32_t sb = smem_u32(smc);

    int gy = blockIdx.y;
    const int* rows = nullptr;
    int cnt;
    if (typed) {
        rows = g_list + g_off[gy];
        cnt = g_cnt[gy];
    } else {
        Xh += (long long)gy * xgys;
        Xl += (long long)gy * xgys;
        cnt = nrows;
    }
    int bm = blockIdx.x * 128;
    if (bm >= cnt) return;

    int tid = threadIdx.x, wid = tid >> 5, lane = tid & 31;
    int warpM = wid & 3, warpN = wid >> 2;
    int rbase = warpM * 32, cbase = warpN * 64;
    int qid = lane >> 2, tq = lane & 3;

    int li = lane & 7, ls = lane >> 3;
    int a_row = li + ((ls & 1) << 3);
    int a_col = ((ls >> 1) & 1) << 3;
    int b_krow = li + ((ls >> 1) << 3);
    int b_ncol = (ls & 1) << 3;

    uint32_t aoff = sb + (uint32_t)(rbase + a_row) * 272u + (uint32_t)a_col * 2u;
    uint32_t boff = sb + M_BH + (uint32_t)b_krow * 272u + (uint32_t)(cbase + b_ncol) * 2u;

    // ---- stage full-K A (4096 16B chunks) ----
    #pragma unroll
    for (int it = 0; it < 16; it++) {
        int s = tid + it * 256;
        int plane = s >> 11, rc = s & 2047;
        int r = rc >> 4, c16 = rc & 15;
        int gr = bm + r;
        int row = (gr < cnt) ? (rows ? rows[gr] : gr) : 0;
        unsigned sz = (gr < cnt) ? 16u : 0u;
        const __half* srcp = (plane ? Xl : Xh) + (long long)row * DD + c16 * 8;
        uint32_t dst = sb + (plane ? M_AL : M_AH) + (uint32_t)r * 272u + (uint32_t)c16 * 16u;
        CPA16(dst, srcp, sz);
    }
    // (first CPA_WAIT below covers A too)

    for (int si = 0; si < args.n; si++) {
        const GMSet& st_ = args.s[si];
        int slot = st_.wslot + (st_.waddgy ? gy : 0);
        const __half* Wh = g_wh + (long long)slot * MSZ;
        const __half* Wl = g_wl + (long long)slot * MSZ;

        float acc[2][8][4];
        #pragma unroll
        for (int mi = 0; mi < 2; mi++)
            #pragma unroll
            for (int ni = 0; ni < 8; ni++)
                #pragma unroll
                for (int j = 0; j < 4; j++) acc[mi][ni][j] = 0.f;

        for (int st = 0; st < 2; st++) {
            __syncthreads();   // prior B reads complete before overwrite
            // stage B(st): 2048 chunks
            #pragma unroll
            for (int it = 0; it < 8; it++) {
                int s = tid + it * 256;
                int plane = s >> 10, rc = s & 1023;
                int k = rc >> 4, c16 = rc & 15;
                const __half* srcp = (plane ? Wl : Wh) + (long long)(st * 64 + k) * DD + c16 * 8;
                uint32_t dst = sb + (plane ? M_BL : M_BH) + (uint32_t)k * 272u + (uint32_t)c16 * 16u;
                CPA16(dst, srcp, 16u);
            }
            CPA_WAIT();
            __syncthreads();

            #pragma unroll
            for (int ks = 0; ks < 4; ks++) {
                uint32_t ka = aoff + (uint32_t)(st * 128 + ks * 32);
                uint32_t ah[2][4], al[2][4];
                LDSM4(ah[0], ka);
                LDSM4(ah[1], ka + 16u * 272u);
                LDSM4(al[0], ka + (uint32_t)M_AL);
                LDSM4(al[1], ka + (uint32_t)M_AL + 16u * 272u);
                #pragma unroll
                for (int nf = 0; nf < 4; nf++) {
                    uint32_t kb = boff + (uint32_t)ks * 4352u + (uint32_t)nf * 32u;
                    uint32_t bhf[4], blf[4];
                    LDSM4T(bhf, kb);
                    LDSM4T(blf, kb + (uint32_t)(M_BL - M_BH));
                    #pragma unroll
                    for (int j = 0; j < 2; j++) {
                        #pragma unroll
                        for (int mi = 0; mi < 2; mi++) {
                            float* a4 = acc[mi][nf * 2 + j];
                            MMA16(a4, ah[mi], bhf[j], bhf[2 + j]);
                            MMA16(a4, al[mi], bhf[j], bhf[2 + j]);
                            MMA16(a4, ah[mi], blf[j], blf[2 + j]);
                        }
                    }
                }
            }
        }

        // epilogue
        const float* bp = st_.bias;
        if (bp && st_.baddgy) bp += (long long)gy * DD;
        float* op = st_.out + (long long)gy * st_.ogys;
        #pragma unroll
        for (int ni = 0; ni < 8; ni++) {
            int col = cbase + ni * 8 + tq * 2;
            float bx = bp ? __ldg(bp + col) : 0.f;
            float by = bp ? __ldg(bp + col + 1) : 0.f;
            #pragma unroll
            for (int mi = 0; mi < 2; mi++) {
                int r0 = bm + rbase + mi * 16 + qid;
                if (r0 < cnt) {
                    int row = rows ? rows[r0] : r0;
                    float2 o = make_float2(acc[mi][ni][0] + bx, acc[mi][ni][1] + by);
                    *(float2*)(op + (long long)row * DD + col) = o;
                }
                int r1 = r0 + 8;
                if (r1 < cnt) {
                    int row = rows ? rows[r1] : r1;
                    float2 o = make_float2(acc[mi][ni][2] + bx, acc[mi][ni][3] + by);
                    *(float2*)(op + (long long)row * DD + col) = o;
                }
            }
        }
    }
}

// ---------------- init (softmax state) ----------------------------------------
__global__ void k_init() {
    int i = blockIdx.x * blockDim.x + threadIdx.x;
    int stride = gridDim.x * blockDim.x;
    for (int j = i; j < NN * HH; j += stride) { g_mx[j] = 0u; g_sum[j] = 0.f; }
    for (int j = i; j < NN; j += stride) g_deg[j] = 0;
}

// ---------------- qA = rel_att-transformed q ----------------------------------
__global__ void k_qA(const float* __restrict__ rel_att) {
    extern __shared__ float Ashm[];
    for (int i = threadIdx.x; i < RR * HH * DKK * DKK; i += blockDim.x) {
        int rh = i >> 10, dm = i & 1023, d = dm >> 5, m = dm & 31;
        Ashm[(rh * 32 + m) * 32 + d] = rel_att[i];
    }
    __syncthreads();
    int lane = threadIdx.x & 31;
    int gw = (blockIdx.x * blockDim.x + threadIdx.x) >> 5;
    int nw = (gridDim.x * blockDim.x) >> 5;
    for (int n = gw; n < NN; n += nw) {
        float qr[HH];
        #pragma unroll
        for (int h = 0; h < HH; h++) qr[h] = g_q[n * DD + h * 32 + lane];
        #pragma unroll
        for (int h = 0; h < HH; h++) {
            float a0 = 0, a1 = 0, a2 = 0, a3 = 0, a4 = 0;
            #pragma unroll
            for (int m = 0; m < 32; m++) {
                float qm = __shfl_sync(0xffffffffu, qr[h], m);
                int base = (h * 32 + m) * 32 + lane;
                a0 += Ashm[base        ] * qm;
                a1 += Ashm[base +  4096] * qm;
                a2 += Ashm[base +  8192] * qm;
                a3 += Ashm[base + 12288] * qm;
                a4 += Ashm[base + 16384] * qm;
            }
            g_qA[((n * RR + 0) * HH + h) * 32 + lane] = a0;
            g_qA[((n * RR + 1) * HH + h) * 32 + lane] = a1;
            g_qA[((n * RR + 2) * HH + h) * 32 + lane] = a2;
            g_qA[((n * RR + 3) * HH + h) * 32 + lane] = a3;
            g_qA[((n * RR + 4) * HH + h) * 32 + lane] = a4;
        }
    }
}

// ---------------- edge logits + segment max + degree ----------------
__global__ void k_logits(const int* __restrict__ ei, const int* __restrict__ et,
                         const float* __restrict__ rel_pri) {
    int lane = threadIdx.x & 31;
    int gw = (blockIdx.x * blockDim.x + threadIdx.x) >> 5;
    int nw = (gridDim.x * blockDim.x) >> 5;
    for (int e = gw; e < EE; e += nw) {
        int s = ei[e], tg = ei[EE + e], r = et[e];
        float p0, p1, p2, p3;
        {
            const float* kb = g_k + (long long)s * DD;
            const float* qa = g_qA + ((long long)tg * RR + r) * DD;
            p0 = kb[lane]      * qa[lane];
            p1 = kb[32 + lane] * qa[32 + lane];
            p2 = kb[64 + lane] * qa[64 + lane];
            p3 = kb[96 + lane] * qa[96 + lane];
        }
        p0 = warp_sum(p0); p1 = warp_sum(p1); p2 = warp_sum(p2); p3 = warp_sum(p3);
        if (lane == 0) {
            atomicAdd(&g_deg[tg], 1);
            float l0 = p0 * rel_pri[r * HH + 0] * INV_SQRT_DK;
            float l1 = p1 * rel_pri[r * HH + 1] * INV_SQRT_DK;
            float l2 = p2 * rel_pri[r * HH + 2] * INV_SQRT_DK;
            float l3 = p3 * rel_pri[r * HH + 3] * INV_SQRT_DK;
            g_logits[e * HH + 0] = l0; g_logits[e * HH + 1] = l1;
            g_logits[e * HH + 2] = l2; g_logits[e * HH + 3] = l3;
            atomicMax(&g_mx[tg * HH + 0], enc_f(l0));
            atomicMax(&g_mx[tg * HH + 1], enc_f(l1));
            atomicMax(&g_mx[tg * HH + 2], enc_f(l2));
            atomicMax(&g_mx[tg * HH + 3], enc_f(l3));
        }
    }
}

// ---------------- exp + segment sum ----------------
__global__ void k_exp(const int* __restrict__ ei) {
    int idx = blockIdx.x * blockDim.x + threadIdx.x;
    if (idx >= EE * HH) return;
    int e = idx >> 2, h = idx & 3;
    int tg = ei[EE + e];
    float ex = expf(g_logits[idx] - dec_f(g_mx[tg * HH + h]));
    g_logits[idx] = ex;
    atomicAdd(&g_sum[tg * HH + h], ex);
}

// ------- messages / agg (edge n < N shortcut); writes SPLIT halves -----------
__global__ void k_msg(const float* __restrict__ rel_msg, const int* __restrict__ ei,
                      const int* __restrict__ et) {
    extern __shared__ float Ms[];
    for (int i = threadIdx.x; i < RR * HH * DKK * DKK; i += blockDim.x) Ms[i] = rel_msg[i];
    __syncthreads();
    int lane = threadIdx.x & 31;
    int gw = (blockIdx.x * blockDim.x + threadIdx.x) >> 5;
    int nw = (gridDim.x * blockDim.x) >> 5;
    for (int n = gw; n < NN; n += nw) {
        int s = ei[n], tg = ei[EE + n], r = et[n];
        float deg = (float)g_deg[n];
        float vr[HH];
        #pragma unroll
        for (int h = 0; h < HH; h++) vr[h] = g_v[(long long)s * DD + h * 32 + lane];
        #pragma unroll
        for (int h = 0; h < HH; h++) {
            float att = g_logits[n * HH + h] / (g_sum[tg * HH + h] + 1e-16f);
            float vp = 0.f;
            const float* Mb = Ms + (r * HH + h) * 1024;
            #pragma unroll
            for (int d = 0; d < 32; d++) {
                float vd = __shfl_sync(0xffffffffu, vr[h], d);
                vp += Mb[d * 32 + lane] * vd;
            }
            float base = deg * att;
            int o = n * DD + h * 32 + lane;
            float vp2 = vp * vp;
            float m1 = base * vp;
            float m2 = base * vp2;
            float m3 = signed_cbrt(base * vp2 * vp);
            __half hh, ll;
            splith(m1, hh, ll); g_aggh[o] = hh;          g_aggl[o] = ll;
            splith(m2, hh, ll); g_aggh[ND + o] = hh;     g_aggl[ND + o] = ll;
            splith(m3, hh, ll); g_aggh[2 * ND + o] = hh; g_aggl[2 * ND + o] = ll;
        }
    }
}

// -- gating: res = sum_k sigmoid(front.tail)*aggm; writes split(gelu(res)) ----
__global__ void k_gate() {
    int w = (blockIdx.x * blockDim.x + threadIdx.x) >> 5;
    int lane = threadIdx.x & 31;
    if (w >= NN) return;
    int o = w * DD + lane * 4;
    float4 r4 = make_float4(0.f, 0.f, 0.f, 0.f);
    #pragma unroll
    for (int k = 0; k < KKM; k++) {
        float4 f = *(float4*)&g_front[k * ND + o];
        float4 t = *(float4*)&g_tail[k * ND + o];
        float p = f.x * t.x + f.y * t.y + f.z * t.z + f.w * t.w;
        p = warp_sum(p);
        float gate = 1.f / (1.f + expf(-p));
        float4 a = *(float4*)&g_aggm[k * ND + o];
        r4.x += gate * a.x; r4.y += gate * a.y; r4.z += gate * a.z; r4.w += gate * a.w;
    }
    float y0 = gelu_exact(r4.x), y1 = gelu_exact(r4.y);
    float y2 = gelu_exact(r4.z), y3 = gelu_exact(r4.w);
    __half h0, h1, h2, h3, l0, l1, l2, l3;
    splith(y0, h0, l0); splith(y1, h1, l1);
    splith(y2, h2, l2); splith(y3, h3, l3);
    *(__half2*)&g_resh[o]     = __halves2half2(h0, h1);
    *(__half2*)&g_resh[o + 2] = __halves2half2(h2, h3);
    *(__half2*)&g_resl[o]     = __halves2half2(l0, l1);
    *(__half2*)&g_resl[o + 2] = __halves2half2(l2, l3);
}

// ---------------- skip blend + LayerNorm --------------------------------------
__global__ void k_postln(const int* __restrict__ nt, const float* __restrict__ xin,
                         const float* __restrict__ skip, const float* __restrict__ lng,
                         const float* __restrict__ lnb, float* __restrict__ out) {
    int wid = (blockIdx.x * blockDim.x + threadIdx.x) >> 5;
    int lane = threadIdx.x & 31;
    if (wid >= NN) return;
    int t = nt[wid];
    float alpha = 1.f / (1.f + expf(-skip[t]));
    int o = wid * DD + lane * 4;
    float4 tr = *(float4*)&g_trans[o];
    float4 xv = *(const float4*)(xin + o);
    float y0 = tr.x * alpha + xv.x * (1.f - alpha);
    float y1 = tr.y * alpha + xv.y * (1.f - alpha);
    float y2 = tr.z * alpha + xv.z * (1.f - alpha);
    float y3 = tr.w * alpha + xv.w * (1.f - alpha);
    float s  = y0 + y1 + y2 + y3;
    float ss = y0 * y0 + y1 * y1 + y2 * y2 + y3 * y3;
    #pragma unroll
    for (int of = 16; of > 0; of >>= 1) {
        s  += __shfl_xor_sync(0xffffffffu, s,  of);
        ss += __shfl_xor_sync(0xffffffffu, ss, of);
    }
    float mu  = s * (1.f / 128.f);
    float inv = rsqrtf(ss * (1.f / 128.f) - mu * mu + 1e-5f);
    float4 gg = *(const float4*)(lng + t * DD + lane * 4);
    float4 bb = *(const float4*)(lnb + t * DD + lane * 4);
    float4 o4;
    o4.x = (y0 - mu) * inv * gg.x + bb.x;
    o4.y = (y1 - mu) * inv * gg.y + bb.y;
    o4.z = (y2 - mu) * inv * gg.z + bb.z;
    o4.w = (y3 - mu) * inv * gg.w + bb.w;
    *(float4*)(out + (long long)wid * DD + lane * 4) = o4;
}

// ---------------- launch ----------------
extern "C" void kernel_launch(void* const* d_in, const int* in_sizes, int n_in,
                              void* d_out, int out_size) {
    const float* meta_xs  = (const float*)d_in[0];
    const int*   node_type= (const int*)  d_in[1];
    const int*   edge_idx = (const int*)  d_in[2];
    const int*   edge_type= (const int*)  d_in[3];
    const float* q_w = (const float*)d_in[5],  *q_b = (const float*)d_in[6];
    const float* k_w = (const float*)d_in[7],  *k_b = (const float*)d_in[8];
    const float* v_w = (const float*)d_in[9],  *v_b = (const float*)d_in[10];
    const float* a_w = (const float*)d_in[11], *a_b = (const float*)d_in[12];
    const float* rel_pri = (const float*)d_in[13];
    const float* rel_att = (const float*)d_in[14];
    const float* rel_msg = (const float*)d_in[15];
    const float* WMk = (const float*)d_in[16];
    const float* Wak = (const float*)d_in[17];
    const float* Wq  = (const float*)d_in[18], *bq  = (const float*)d_in[19];
    const float* Wkl = (const float*)d_in[20], *bkl = (const float*)d_in[21];
    const float* skip= (const float*)d_in[22];
    const float* lng = (const float*)d_in[23], *lnb = (const float*)d_in[24];
    float* out = (float*)d_out;

    cudaFuncSetAttribute(k_qA,       cudaFuncAttributeMaxDynamicSharedMemorySize, 81920);
    cudaFuncSetAttribute(k_msg,      cudaFuncAttributeMaxDynamicSharedMemorySize, 81920);
    cudaFuncSetAttribute(tc_gemm_ms, cudaFuncAttributeMaxDynamicSharedMemorySize, GSM_MS);

    void *pq, *pk, *pv, *paggm, *pfront, *ptail, *ptrans, *pbf;
    void *pxh, *pxl, *paggh, *paggl, *presh, *presl;
    cudaGetSymbolAddress(&pq, g_q);
    cudaGetSymbolAddress(&pk, g_k);
    cudaGetSymbolAddress(&pv, g_v);
    cudaGetSymbolAddress(&paggm, g_aggm);
    cudaGetSymbolAddress(&pfront, g_front);
    cudaGetSymbolAddress(&ptail, g_tail);
    cudaGetSymbolAddress(&ptrans, g_trans);
    cudaGetSymbolAddress(&pbf, g_bf);
    cudaGetSymbolAddress(&pxh, g_xh);
    cudaGetSymbolAddress(&pxl, g_xl);
    cudaGetSymbolAddress(&paggh, g_aggh);
    cudaGetSymbolAddress(&paggl, g_aggl);
    cudaGetSymbolAddress(&presh, g_resh);
    cudaGetSymbolAddress(&presl, g_resl);

    // 1-3: bucketing (no pre-zero needed)
    k_count<<<NPART, 256>>>(node_type);
    k_offs<<<1, 96>>>();
    k_scatter<<<NPART, 256>>>(node_type);

    // 4: exact fp32 weight combines + bf
    wcomb_all<<<dim3(2, 7), 256>>>(WMk, Wkl, Wq, Wak, bq);

    // 5: presplit x + all 21 weight matrices
    {
        long long total = (long long)ND + 21LL * MSZ;
        k_splitall<<<(unsigned)((total + 255) / 256), 256>>>(meta_xs, q_w, k_w, v_w, a_w, WMk);
    }

    dim3 gT((NN + 127) / 128, TT);
    dim3 gK((NN + 127) / 128, KKM);
    __half* xh = (__half*)pxh; __half* xl = (__half*)pxl;

    // 6: merged q/k/v/front GEMM (typed; shares gathered A) <- ncu captures this
    {
        GMArgs a;
        a.n = 6;
        a.s[0] = { 0, 1, q_b, 1, (float*)pq, 0 };
        a.s[1] = { 3, 1, k_b, 1, (float*)pk, 0 };
        a.s[2] = { 6, 1, v_b, 1, (float*)pv, 0 };
        a.s[3] = { 18, 0, (const float*)pbf,            0, (float*)pfront, 0 };
        a.s[4] = { 19, 0, (const float*)pbf + DD,       0, (float*)pfront + (long long)ND, 0 };
        a.s[5] = { 20, 0, (const float*)pbf + 2 * DD,   0, (float*)pfront + 2LL * ND, 0 };
        tc_gemm_ms<<<gT, 256, GSM_MS>>>(xh, xl, 0, 1, 0, a);
    }

    // 7: softmax-state init
    k_init<<<512, 256>>>();

    // 8-11: edge pipeline
    k_qA<<<592, 256, 81920>>>(rel_att);
    k_logits<<<2368, 256>>>(edge_idx, edge_type, rel_pri);
    k_exp<<<(EE * HH + 255) / 256, 256>>>(edge_idx);
    k_msg<<<592, 256, 81920>>>(rel_msg, edge_idx, edge_type);

    // 12: merged aggm/tail GEMM (y = moment k; shares agg A)
    {
        GMArgs a;
        a.n = 2;
        a.s[0] = { 12, 1, nullptr, 0, (float*)paggm, (long long)ND };
        a.s[1] = { 15, 1, bkl,     0, (float*)ptail, (long long)ND };
        tc_gemm_ms<<<gK, 256, GSM_MS>>>((__half*)paggh, (__half*)paggl, (long long)ND, 0, NN, a);
    }

    // 13: gating -> split(gelu(res))
    k_gate<<<(NN * 32 + 255) / 256, 256>>>();

    // 14: trans = typed a_w GEMM over gelu(res)
    {
        GMArgs a;
        a.n = 1;
        a.s[0] = { 9, 1, a_b, 1, (float*)ptrans, 0 };
        tc_gemm_ms<<<gT, 256, GSM_MS>>>((__half*)presh, (__half*)presl, 0, 1, 0, a);
    }

    // 15: skip blend + LayerNorm
    k_postln<<<(NN * 32 + 255) / 256, 256>>>(node_type, meta_xs, skip, lng, lnb, out);
}